// round 1
// baseline (speedup 1.0000x reference)
#include <cuda_runtime.h>
#include <math.h>

#define BB 2
#define TT 2048
#define CC 2048
#define HH 16
#define DD 128
#define MM (BB*TT)        // 4096 rows
#define NQKV (3*CC)       // 6144

// ---------------- scratch (alloc-free: __device__ globals) ----------------
static __device__ float g_Q[(size_t)BB*HH*TT*DD];   // 33.5 MB, [b,h,t,d]
static __device__ float g_K[(size_t)BB*HH*TT*DD];
static __device__ float g_V[(size_t)BB*HH*TT*DD];
static __device__ float g_attn[(size_t)MM*CC];      // [b*T, C] attn output
static __device__ float g_cos[TT*(DD/2)];
static __device__ float g_sin[TT*(DD/2)];

// ---------------- RoPE tables ----------------
__global__ void rope_init_kernel() {
    int idx = blockIdx.x * blockDim.x + threadIdx.x;
    if (idx >= TT*(DD/2)) return;
    int t = idx / (DD/2);
    int i = idx - t*(DD/2);
    float inv = powf(10000.0f, -(float)(2*i) / (float)DD);
    float ang = (float)t * inv;
    g_cos[idx] = cosf(ang);
    g_sin[idx] = sinf(ang);
}

// ---------------- SGEMM 128x128x16, 8x8 microtile, reg prefetch ----------------
// EPI==1: qkv epilogue (bias + RoPE + scatter to g_Q/g_K/g_V)
// EPI==0: plain epilogue (bias + write to out), A taken from g_attn if A_ATTN
template<int NCOLS, int EPI, bool A_ATTN>
__global__ __launch_bounds__(256, 2) void gemm_kernel(
    const float* __restrict__ A_in, const float* __restrict__ Bm,
    const float* __restrict__ bias, float* __restrict__ out)
{
    __shared__ float As[16][132];   // transposed A tile (+pad)
    __shared__ float Bs[16][128];

    const float* A = A_ATTN ? g_attn : A_in;
    const int tid = threadIdx.x;
    const int tx  = tid & 15;       // 16 col-groups
    const int ty  = tid >> 4;       // 16 row-groups
    const int bn  = blockIdx.x, bm = blockIdx.y;

    const int aRow = tid >> 2;          // 0..63
    const int aCol = (tid & 3) << 2;    // 0,4,8,12
    const int bRow = tid >> 5;          // 0..7
    const int bCol = (tid & 31) << 2;   // 0..124

    const float* Ap = A  + (size_t)bm * 128 * CC;
    const float* Bp = Bm + (size_t)bn * 128;

    float acc[8][8];
    #pragma unroll
    for (int i = 0; i < 8; i++)
        #pragma unroll
        for (int j = 0; j < 8; j++) acc[i][j] = 0.f;

    // preload tile k0=0 into regs
    float4 a0 = *(const float4*)(Ap + (size_t)aRow*CC + aCol);
    float4 a1 = *(const float4*)(Ap + (size_t)(aRow+64)*CC + aCol);
    float4 b0 = *(const float4*)(Bp + (size_t)bRow*NCOLS + bCol);
    float4 b1 = *(const float4*)(Bp + (size_t)(bRow+8)*NCOLS + bCol);

    for (int k0 = 0; k0 < CC; k0 += 16) {
        __syncthreads();
        As[aCol+0][aRow]    = a0.x; As[aCol+1][aRow]    = a0.y;
        As[aCol+2][aRow]    = a0.z; As[aCol+3][aRow]    = a0.w;
        As[aCol+0][aRow+64] = a1.x; As[aCol+1][aRow+64] = a1.y;
        As[aCol+2][aRow+64] = a1.z; As[aCol+3][aRow+64] = a1.w;
        *(float4*)&Bs[bRow][bCol]   = b0;
        *(float4*)&Bs[bRow+8][bCol] = b1;
        __syncthreads();
        if (k0 + 16 < CC) {   // prefetch next tile (overlaps compute)
            a0 = *(const float4*)(Ap + (size_t)aRow*CC + (k0+16) + aCol);
            a1 = *(const float4*)(Ap + (size_t)(aRow+64)*CC + (k0+16) + aCol);
            b0 = *(const float4*)(Bp + (size_t)(k0+16+bRow)*NCOLS + bCol);
            b1 = *(const float4*)(Bp + (size_t)(k0+16+bRow+8)*NCOLS + bCol);
        }
        #pragma unroll
        for (int kk = 0; kk < 16; kk++) {
            float ar[8], br[8];
            *(float4*)&ar[0] = *(const float4*)&As[kk][ty*8];
            *(float4*)&ar[4] = *(const float4*)&As[kk][ty*8+4];
            *(float4*)&br[0] = *(const float4*)&Bs[kk][tx*4];        // cols tx*4..+3
            *(float4*)&br[4] = *(const float4*)&Bs[kk][64 + tx*4];   // cols 64+tx*4..+3
            #pragma unroll
            for (int i = 0; i < 8; i++)
                #pragma unroll
                for (int j = 0; j < 8; j++)
                    acc[i][j] = fmaf(ar[i], br[j], acc[i][j]);
        }
    }

    const int colBase = bn * 128;
    if (EPI == 0) {
        #pragma unroll
        for (int i = 0; i < 8; i++) {
            size_t r = (size_t)bm*128 + ty*8 + i;
            float4 o0, o1;
            o0.x = acc[i][0] + bias[colBase + tx*4 + 0];
            o0.y = acc[i][1] + bias[colBase + tx*4 + 1];
            o0.z = acc[i][2] + bias[colBase + tx*4 + 2];
            o0.w = acc[i][3] + bias[colBase + tx*4 + 3];
            o1.x = acc[i][4] + bias[colBase + 64 + tx*4 + 0];
            o1.y = acc[i][5] + bias[colBase + 64 + tx*4 + 1];
            o1.z = acc[i][6] + bias[colBase + 64 + tx*4 + 2];
            o1.w = acc[i][7] + bias[colBase + 64 + tx*4 + 3];
            *(float4*)(out + r*NCOLS + colBase + tx*4)      = o0;
            *(float4*)(out + r*NCOLS + colBase + 64 + tx*4) = o1;
        }
    } else {
        // a 128-col tile is exactly one head of one of {Q,K,V}
        const int which = colBase / CC;
        const int h     = (colBase % CC) / DD;
        float* basep = (which == 0) ? g_Q : (which == 1) ? g_K : g_V;
        #pragma unroll
        for (int i = 0; i < 8; i++) {
            int r = bm*128 + ty*8 + i;
            int b = r / TT;
            int t = r - b*TT;
            float v[8];
            #pragma unroll
            for (int j = 0; j < 4; j++) v[j]   = acc[i][j]   + bias[colBase + tx*4 + j];
            #pragma unroll
            for (int j = 0; j < 4; j++) v[4+j] = acc[i][4+j] + bias[colBase + 64 + tx*4 + j];
            if (which != 2) {
                #pragma unroll
                for (int g = 0; g < 2; g++) {
                    int dbase = g ? (64 + tx*4) : (tx*4);
                    #pragma unroll
                    for (int j = 0; j < 4; j += 2) {
                        int d = dbase + j;
                        float c = g_cos[t*(DD/2) + (d >> 1)];
                        float s = g_sin[t*(DD/2) + (d >> 1)];
                        float x1 = v[g*4+j], x2 = v[g*4+j+1];
                        v[g*4+j]   = x1*c - x2*s;
                        v[g*4+j+1] = x1*s + x2*c;
                    }
                }
            }
            float* dst = basep + (((size_t)(b*HH + h))*TT + t)*DD;
            *(float4*)(dst + tx*4)      = make_float4(v[0], v[1], v[2], v[3]);
            *(float4*)(dst + 64 + tx*4) = make_float4(v[4], v[5], v[6], v[7]);
        }
    }
}

// ---------------- causal flash attention, 64x64 tiles, fp32 ----------------
// smem: Qt[128][68] (D-major), KV union (Kt[128][68] / Vs[64][128]), Ps[64][64]
#define QT_STR 68
#define ATTN_SMEM ((128*QT_STR + 128*QT_STR + 64*64) * 4)

__global__ __launch_bounds__(256, 2) void attn_kernel() {
    extern __shared__ float sm[];
    float* Qt = sm;                    // [d][i], stride 68
    float* KV = sm + 128*QT_STR;       // Kt [d][j] stride 68  /  Vs [j][d] stride 128
    float* Ps = KV + 128*QT_STR;       // [i][j], stride 64

    const int tid = threadIdx.x;
    const int tx  = tid & 15;          // key-col group / d group
    const int ty  = tid >> 4;          // query-row group
    const int bh  = blockIdx.y;
    const int q0  = (int)(gridDim.x - 1 - blockIdx.x) * 64;  // heavy tiles first

    const float* Q = g_Q + (size_t)bh*TT*DD;
    const float* K = g_K + (size_t)bh*TT*DD;
    const float* V = g_V + (size_t)bh*TT*DD;

    // load Q tile transposed
    #pragma unroll
    for (int p = 0; p < 8; p++) {
        int idx = tid + p*256;
        int row = idx >> 5;
        int col = (idx & 31) << 2;
        float4 qv = *(const float4*)(Q + (size_t)(q0+row)*DD + col);
        Qt[(col+0)*QT_STR + row] = qv.x;
        Qt[(col+1)*QT_STR + row] = qv.y;
        Qt[(col+2)*QT_STR + row] = qv.z;
        Qt[(col+3)*QT_STR + row] = qv.w;
    }

    float m_i[4], l_i[4], O[4][8];
    #pragma unroll
    for (int ii = 0; ii < 4; ii++) {
        m_i[ii] = -1e30f; l_i[ii] = 0.f;
        #pragma unroll
        for (int dd = 0; dd < 8; dd++) O[ii][dd] = 0.f;
    }

    const int i0 = ty*4, j0 = tx*4;
    const float scale = 0.08838834764831845f;  // 1/sqrt(128)

    for (int k0 = 0; k0 <= q0; k0 += 64) {
        __syncthreads();   // prev PV done with KV/Ps (also guards Qt on iter 0 path below)
        // load K tile transposed
        #pragma unroll
        for (int p = 0; p < 8; p++) {
            int idx = tid + p*256;
            int row = idx >> 5;
            int col = (idx & 31) << 2;
            float4 kv = *(const float4*)(K + (size_t)(k0+row)*DD + col);
            KV[(col+0)*QT_STR + row] = kv.x;
            KV[(col+1)*QT_STR + row] = kv.y;
            KV[(col+2)*QT_STR + row] = kv.z;
            KV[(col+3)*QT_STR + row] = kv.w;
        }
        __syncthreads();

        // S = Q K^T   (4x4 per thread)
        float s[4][4];
        #pragma unroll
        for (int ii = 0; ii < 4; ii++)
            #pragma unroll
            for (int jj = 0; jj < 4; jj++) s[ii][jj] = 0.f;
        #pragma unroll 8
        for (int d = 0; d < 128; d++) {
            float4 q4 = *(const float4*)&Qt[d*QT_STR + i0];
            float4 k4 = *(const float4*)&KV[d*QT_STR + j0];
            float qa[4] = {q4.x, q4.y, q4.z, q4.w};
            float ka[4] = {k4.x, k4.y, k4.z, k4.w};
            #pragma unroll
            for (int ii = 0; ii < 4; ii++)
                #pragma unroll
                for (int jj = 0; jj < 4; jj++)
                    s[ii][jj] = fmaf(qa[ii], ka[jj], s[ii][jj]);
        }
        const bool diag = (k0 == q0);
        #pragma unroll
        for (int ii = 0; ii < 4; ii++)
            #pragma unroll
            for (int jj = 0; jj < 4; jj++) {
                s[ii][jj] *= scale;
                if (diag && (k0 + j0 + jj > q0 + i0 + ii)) s[ii][jj] = -1e30f;
            }

        // online softmax (row reductions across the 16 tx-lanes, width-16 shfl)
        #pragma unroll
        for (int ii = 0; ii < 4; ii++) {
            float mx = fmaxf(fmaxf(s[ii][0], s[ii][1]), fmaxf(s[ii][2], s[ii][3]));
            #pragma unroll
            for (int off = 8; off > 0; off >>= 1)
                mx = fmaxf(mx, __shfl_xor_sync(0xffffffffu, mx, off, 16));
            float mnew = fmaxf(m_i[ii], mx);
            float p0 = __expf(s[ii][0] - mnew);
            float p1 = __expf(s[ii][1] - mnew);
            float p2 = __expf(s[ii][2] - mnew);
            float p3 = __expf(s[ii][3] - mnew);
            float rs = p0 + p1 + p2 + p3;
            #pragma unroll
            for (int off = 8; off > 0; off >>= 1)
                rs += __shfl_xor_sync(0xffffffffu, rs, off, 16);
            float alpha = __expf(m_i[ii] - mnew);
            l_i[ii] = l_i[ii]*alpha + rs;
            m_i[ii] = mnew;
            #pragma unroll
            for (int dd = 0; dd < 8; dd++) O[ii][dd] *= alpha;
            *(float4*)&Ps[(i0+ii)*64 + j0] = make_float4(p0, p1, p2, p3);
        }
        __syncthreads();   // all done reading Kt before V overwrites it

        // load V tile (plain [j][d])
        #pragma unroll
        for (int p = 0; p < 8; p++) {
            int idx = tid + p*256;
            int row = idx >> 5;
            int col = (idx & 31) << 2;
            *(float4*)&KV[row*128 + col] =
                *(const float4*)(V + (size_t)(k0+row)*DD + col);
        }
        __syncthreads();

        // O += P V   (each thread: 4 rows x {tx*4..+3, 64+tx*4..+3})
        #pragma unroll 2
        for (int j = 0; j < 64; j++) {
            float4 v0 = *(const float4*)&KV[j*128 + tx*4];
            float4 v1 = *(const float4*)&KV[j*128 + 64 + tx*4];
            #pragma unroll
            for (int ii = 0; ii < 4; ii++) {
                float p = Ps[(i0+ii)*64 + j];
                O[ii][0] = fmaf(p, v0.x, O[ii][0]);
                O[ii][1] = fmaf(p, v0.y, O[ii][1]);
                O[ii][2] = fmaf(p, v0.z, O[ii][2]);
                O[ii][3] = fmaf(p, v0.w, O[ii][3]);
                O[ii][4] = fmaf(p, v1.x, O[ii][4]);
                O[ii][5] = fmaf(p, v1.y, O[ii][5]);
                O[ii][6] = fmaf(p, v1.z, O[ii][6]);
                O[ii][7] = fmaf(p, v1.w, O[ii][7]);
            }
        }
    }

    // write attn output: [b*T + q, h*D + d]
    const int b = bh / HH, h = bh % HH;
    #pragma unroll
    for (int ii = 0; ii < 4; ii++) {
        float inv = 1.0f / l_i[ii];
        int q = q0 + i0 + ii;
        float* dst = g_attn + ((size_t)(b*TT + q))*CC + h*DD;
        *(float4*)(dst + tx*4) =
            make_float4(O[ii][0]*inv, O[ii][1]*inv, O[ii][2]*inv, O[ii][3]*inv);
        *(float4*)(dst + 64 + tx*4) =
            make_float4(O[ii][4]*inv, O[ii][5]*inv, O[ii][6]*inv, O[ii][7]*inv);
    }
}

// ---------------- launcher ----------------
extern "C" void kernel_launch(void* const* d_in, const int* in_sizes, int n_in,
                              void* d_out, int out_size) {
    const float* x      = (const float*)d_in[0];
    const float* W_attn = (const float*)d_in[1];
    const float* b_attn = (const float*)d_in[2];
    const float* W_proj = (const float*)d_in[3];
    const float* b_proj = (const float*)d_in[4];
    float* out = (float*)d_out;

    cudaFuncSetAttribute(attn_kernel,
                         cudaFuncAttributeMaxDynamicSharedMemorySize, ATTN_SMEM);

    rope_init_kernel<<<(TT*(DD/2) + 255)/256, 256>>>();

    gemm_kernel<NQKV, 1, false><<<dim3(NQKV/128, MM/128), 256>>>(x, W_attn, b_attn, nullptr);

    attn_kernel<<<dim3(TT/64, BB*HH), 256, ATTN_SMEM>>>();

    gemm_kernel<CC, 0, true><<<dim3(CC/128, MM/128), 256>>>(nullptr, W_proj, b_proj, out);
}

// round 7
// speedup vs baseline: 1.0478x; 1.0478x over previous
#include <cuda_runtime.h>
#include <cuda_bf16.h>
#include <math.h>
#include <cstdint>

#define BB 2
#define TT 2048
#define CC 2048
#define HH 16
#define DD 128
#define MM (BB*TT)        // 4096
#define NQKV (3*CC)       // 6144

// ---------------- scratch (alloc-free: __device__ globals) ----------------
// RULE (R5 root cause): NEVER pass these as kernel arguments from host code.
// Host sees the shadow symbol; with ATS on GB300 the GPU silently writes host RAM.
// All references below are from device code via template selection.
static __device__ __align__(256) float g_Q[(size_t)BB*HH*TT*DD];
static __device__ __align__(256) float g_K[(size_t)BB*HH*TT*DD];
static __device__ __align__(256) float g_V[(size_t)BB*HH*TT*DD];
static __device__ __align__(256) float g_qkv[(size_t)MM*NQKV];
static __device__ __align__(256) float g_attn[(size_t)MM*CC];
static __device__ __align__(256) float g_cos[TT*(DD/2)];
static __device__ __align__(256) float g_sin[TT*(DD/2)];
static __device__ int g_flag[2];
static __device__ __align__(256) __nv_bfloat16 g_Xh [(size_t)MM*CC],   g_Xl [(size_t)MM*CC];
static __device__ __align__(256) __nv_bfloat16 g_Wqh[(size_t)NQKV*CC], g_Wql[(size_t)NQKV*CC];
static __device__ __align__(256) __nv_bfloat16 g_Wph[(size_t)CC*CC],   g_Wpl[(size_t)CC*CC];
static __device__ __align__(256) __nv_bfloat16 g_AOh[(size_t)MM*CC],   g_AOl[(size_t)MM*CC];

__device__ __forceinline__ void mma16816(float* c, const uint32_t* a, const uint32_t* b){
    asm volatile("mma.sync.aligned.m16n8k16.row.col.f32.bf16.bf16.f32 "
                 "{%0,%1,%2,%3}, {%4,%5,%6,%7}, {%8,%9}, {%0,%1,%2,%3};"
                 : "+f"(c[0]), "+f"(c[1]), "+f"(c[2]), "+f"(c[3])
                 : "r"(a[0]), "r"(a[1]), "r"(a[2]), "r"(a[3]), "r"(b[0]), "r"(b[1]));
}

// ---------------- init ----------------
__global__ void reset_flags_kernel() { if (threadIdx.x < 2) g_flag[threadIdx.x] = 0; }

__global__ void rope_init_kernel() {
    int idx = blockIdx.x * blockDim.x + threadIdx.x;
    if (idx >= TT*(DD/2)) return;
    int t = idx / (DD/2);
    int i = idx - t*(DD/2);
    float inv = powf(10000.0f, -(float)(2*i) / (float)DD);
    float ang = (float)t * inv;
    g_cos[idx] = cosf(ang);
    g_sin[idx] = sinf(ang);
}

// ---------------- conversions (dst selected in DEVICE code) ----------------
// SEL 0: x (param) -> g_Xh/g_Xl ; SEL 1: g_attn -> g_AOh/g_AOl
template<int SEL>
__global__ void conv_split_kernel(const float* __restrict__ xin) {
    int i = blockIdx.x * blockDim.x + threadIdx.x;
    if (i >= MM*CC/2) return;
    const float* src = (SEL == 0) ? xin : g_attn;
    __nv_bfloat16* dh = (SEL == 0) ? g_Xh : g_AOh;
    __nv_bfloat16* dl = (SEL == 0) ? g_Xl : g_AOl;
    float2 v = ((const float2*)src)[i];
    __nv_bfloat16 h0 = __float2bfloat16(v.x), h1 = __float2bfloat16(v.y);
    __nv_bfloat16 l0 = __float2bfloat16(v.x - __bfloat162float(h0));
    __nv_bfloat16 l1 = __float2bfloat16(v.y - __bfloat162float(h1));
    ((__nv_bfloat162*)dh)[i] = __halves2bfloat162(h0, h1);
    ((__nv_bfloat162*)dl)[i] = __halves2bfloat162(l0, l1);
}

// W[k][N] fp32 -> (g_Wqh/g_Wql or g_Wph/g_Wpl)[n][2048] bf16 (transpose + split)
template<int SEL>
__global__ void conv_wT_kernel(const float* __restrict__ W) {
    constexpr int N = (SEL == 0) ? NQKV : CC;
    __nv_bfloat16* oh = (SEL == 0) ? g_Wqh : g_Wph;
    __nv_bfloat16* ol = (SEL == 0) ? g_Wql : g_Wpl;
    __shared__ float t[32][33];
    int k0 = blockIdx.y * 32, n0 = blockIdx.x * 32;
    int tid = threadIdx.x;
    #pragma unroll
    for (int r = 0; r < 4; r++) {
        int kk = (tid >> 5) + r*8, nn = tid & 31;
        t[kk][nn] = W[(size_t)(k0+kk)*N + n0 + nn];
    }
    __syncthreads();
    int nn = tid >> 3, ks = (tid & 7) * 4;
    size_t base = (size_t)(n0+nn)*CC + k0 + ks;
    float v[4];
    #pragma unroll
    for (int j = 0; j < 4; j++) v[j] = t[ks+j][nn];
    __nv_bfloat16 h[4], l[4];
    #pragma unroll
    for (int j = 0; j < 4; j++) {
        h[j] = __float2bfloat16(v[j]);
        l[j] = __float2bfloat16(v[j] - __bfloat162float(h[j]));
    }
    *(__nv_bfloat162*)(oh + base)     = __halves2bfloat162(h[0], h[1]);
    *(__nv_bfloat162*)(oh + base + 2) = __halves2bfloat162(h[2], h[3]);
    *(__nv_bfloat162*)(ol + base)     = __halves2bfloat162(l[0], l[1]);
    *(__nv_bfloat162*)(ol + base + 2) = __halves2bfloat162(l[2], l[3]);
}

// ---------------- vanilla bf16x3 mma GEMM: CTA 128x128, warp 32x64, K-slice 32 ----------------
#define TILE_B 10240          // 128 rows * 80B
#define BUF_B  (4*TILE_B)     // Ah|Al|Bh|Bl
#define GEMM_SMEM (2*BUF_B)   // 81920

template<int PHASE>
__global__ __launch_bounds__(256, 1)
void gemm_mma(const float* __restrict__ bias, float* __restrict__ out_p)
{
    constexpr int Ntot = (PHASE == 0) ? NQKV : CC;
    const __nv_bfloat16* __restrict__ pAh = (PHASE == 0) ? g_Xh  : g_AOh;
    const __nv_bfloat16* __restrict__ pAl = (PHASE == 0) ? g_Xl  : g_AOl;
    const __nv_bfloat16* __restrict__ pBh = (PHASE == 0) ? g_Wqh : g_Wph;
    const __nv_bfloat16* __restrict__ pBl = (PHASE == 0) ? g_Wql : g_Wpl;
    float* __restrict__ out = (PHASE == 0) ? g_qkv : out_p;

    extern __shared__ char smraw[];
    const int tid  = threadIdx.x;
    const int lane = tid & 31;
    const int wid  = tid >> 5;
    const int wm   = wid & 3;
    const int wn   = wid >> 2;

    const int nT = Ntot / 128;
    int id  = blockIdx.x;
    int gsz = 8 * nT;
    int bm  = (id / gsz) * 8 + (id % gsz) % 8;
    int bn  = (id % gsz) / 8;
    const int m0 = bm * 128, n0 = bn * 128;

    const int r0 = tid >> 2, sg = tid & 3;
    const size_t aoff = (size_t)(m0 + r0)*CC + sg*8;
    const size_t boff = (size_t)(n0 + r0)*CC + sg*8;
    const uint32_t so = (uint32_t)(r0*80 + sg*16);

    float4 sAh0, sAh1, sAl0, sAl1, sBh0, sBh1, sBl0, sBl1;
    auto fetch = [&](int s) {
        size_t ks = (size_t)s*32;
        sAh0 = *(const float4*)(pAh + aoff + ks);
        sAh1 = *(const float4*)(pAh + aoff + (size_t)64*CC + ks);
        sAl0 = *(const float4*)(pAl + aoff + ks);
        sAl1 = *(const float4*)(pAl + aoff + (size_t)64*CC + ks);
        sBh0 = *(const float4*)(pBh + boff + ks);
        sBh1 = *(const float4*)(pBh + boff + (size_t)64*CC + ks);
        sBl0 = *(const float4*)(pBl + boff + ks);
        sBl1 = *(const float4*)(pBl + boff + (size_t)64*CC + ks);
    };
    auto deposit = [&](int b) {
        char* base = smraw + b*BUF_B;
        *(float4*)(base +            so) = sAh0;  *(float4*)(base +            so + 5120) = sAh1;
        *(float4*)(base +   TILE_B + so) = sAl0;  *(float4*)(base +   TILE_B + so + 5120) = sAl1;
        *(float4*)(base + 2*TILE_B + so) = sBh0;  *(float4*)(base + 2*TILE_B + so + 5120) = sBh1;
        *(float4*)(base + 3*TILE_B + so) = sBl0;  *(float4*)(base + 3*TILE_B + so + 5120) = sBl1;
    };

    float acc[2][8][4];
    #pragma unroll
    for (int mt = 0; mt < 2; mt++)
        #pragma unroll
        for (int nt = 0; nt < 8; nt++)
            #pragma unroll
            for (int q = 0; q < 4; q++) acc[mt][nt][q] = 0.f;

    const int NS = CC / 32;   // 64
    fetch(0);
    for (int s = 0; s < NS; s++) {
        int buf = s & 1;
        deposit(buf);
        __syncthreads();
        if (s + 1 < NS) fetch(s + 1);

        const char* cAh = smraw + buf*BUF_B;
        const char* cAl = cAh + TILE_B;
        const char* cBh = cAh + 2*TILE_B;
        const char* cBl = cAh + 3*TILE_B;

        #pragma unroll
        for (int kc = 0; kc < 2; kc++) {
            uint32_t ah[2][4], al[2][4], bh[8][2], bl[8][2];
            #pragma unroll
            for (int mt = 0; mt < 2; mt++) {
                uint32_t fr = (uint32_t)((wm*32 + mt*16 + (lane>>2))*80 + kc*32 + (lane&3)*4);
                ah[mt][0] = *(const uint32_t*)(cAh + fr);
                ah[mt][1] = *(const uint32_t*)(cAh + fr + 8*80);
                ah[mt][2] = *(const uint32_t*)(cAh + fr + 16);
                ah[mt][3] = *(const uint32_t*)(cAh + fr + 8*80 + 16);
                al[mt][0] = *(const uint32_t*)(cAl + fr);
                al[mt][1] = *(const uint32_t*)(cAl + fr + 8*80);
                al[mt][2] = *(const uint32_t*)(cAl + fr + 16);
                al[mt][3] = *(const uint32_t*)(cAl + fr + 8*80 + 16);
            }
            #pragma unroll
            for (int nt = 0; nt < 8; nt++) {
                uint32_t fb = (uint32_t)((wn*64 + nt*8 + (lane>>2))*80 + kc*32 + (lane&3)*4);
                bh[nt][0] = *(const uint32_t*)(cBh + fb);
                bh[nt][1] = *(const uint32_t*)(cBh + fb + 16);
                bl[nt][0] = *(const uint32_t*)(cBl + fb);
                bl[nt][1] = *(const uint32_t*)(cBl + fb + 16);
            }
            #pragma unroll
            for (int mt = 0; mt < 2; mt++)
                #pragma unroll
                for (int nt = 0; nt < 8; nt++) {
                    mma16816(acc[mt][nt], ah[mt], bh[nt]);
                    mma16816(acc[mt][nt], ah[mt], bl[nt]);
                    mma16816(acc[mt][nt], al[mt], bh[nt]);
                }
        }
        __syncthreads();
    }

    const int gid = lane >> 2, tig = lane & 3;
    #pragma unroll
    for (int mt = 0; mt < 2; mt++) {
        int m = m0 + wm*32 + mt*16 + gid;
        #pragma unroll
        for (int nt = 0; nt < 8; nt++) {
            int n = n0 + wn*64 + nt*8 + tig*2;
            float bv0 = bias[n], bv1 = bias[n+1];
            *(float2*)(out + (size_t)m*Ntot + n)     = make_float2(acc[mt][nt][0] + bv0, acc[mt][nt][1] + bv1);
            *(float2*)(out + (size_t)(m+8)*Ntot + n) = make_float2(acc[mt][nt][2] + bv0, acc[mt][nt][3] + bv1);
        }
    }
}

// ---------------- deterministic spot-check (A / C selected in DEVICE code) ----------------
template<int PHASE>
__global__ void check_kernel(const float* __restrict__ Afp_p, const float* __restrict__ Wfp,
                             const float* __restrict__ bias, const float* __restrict__ Cres_p)
{
    constexpr int Ntot = (PHASE == 0) ? NQKV : CC;
    const float* Afp  = (PHASE == 0) ? Afp_p : g_attn;
    const float* Cres = (PHASE == 0) ? g_qkv : Cres_p;
    unsigned id = blockIdx.x * blockDim.x + threadIdx.x;   // 2048 samples
    int m = (int)((id * 2654435761u) % (unsigned)MM);
    int n = (int)((id * 805306457u + 12345u) % (unsigned)Ntot);
    float ref = bias[n];
    const float* arow = Afp + (size_t)m*CC;
    #pragma unroll 4
    for (int k = 0; k < CC; k++)
        ref += arow[k] * Wfp[(size_t)k*Ntot + n];
    float got = Cres[(size_t)m*Ntot + n];
    float rel = fabsf(got - ref) / (fabsf(ref) + 1.0f);
    if (!(rel < 2e-2f)) g_flag[PHASE] = 1;
}

// ---------------- fallback: R1-proven fp32 SGEMM (runs only if flag set) ----------------
template<int PHASE>
__global__ __launch_bounds__(256, 2) void gemm_fb(
    const float* __restrict__ A_p, const float* __restrict__ Bm,
    const float* __restrict__ bias, float* __restrict__ out_p)
{
    if (g_flag[PHASE] == 0) return;
    constexpr int NCOLS = (PHASE == 0) ? NQKV : CC;
    const float* A = (PHASE == 0) ? A_p : g_attn;
    float* out     = (PHASE == 0) ? g_qkv : out_p;

    __shared__ float As[16][132];
    __shared__ float Bs[16][128];

    const int tid = threadIdx.x;
    const int tx  = tid & 15;
    const int ty  = tid >> 4;
    const int bn  = blockIdx.x, bm = blockIdx.y;

    const int aRow = tid >> 2;
    const int aCol = (tid & 3) << 2;
    const int bRow = tid >> 5;
    const int bCol = (tid & 31) << 2;

    const float* Ap = A  + (size_t)bm * 128 * CC;
    const float* Bp = Bm + (size_t)bn * 128;

    float acc[8][8];
    #pragma unroll
    for (int i = 0; i < 8; i++)
        #pragma unroll
        for (int j = 0; j < 8; j++) acc[i][j] = 0.f;

    float4 a0 = *(const float4*)(Ap + (size_t)aRow*CC + aCol);
    float4 a1 = *(const float4*)(Ap + (size_t)(aRow+64)*CC + aCol);
    float4 b0 = *(const float4*)(Bp + (size_t)bRow*NCOLS + bCol);
    float4 b1 = *(const float4*)(Bp + (size_t)(bRow+8)*NCOLS + bCol);

    for (int k0 = 0; k0 < CC; k0 += 16) {
        __syncthreads();
        As[aCol+0][aRow]    = a0.x; As[aCol+1][aRow]    = a0.y;
        As[aCol+2][aRow]    = a0.z; As[aCol+3][aRow]    = a0.w;
        As[aCol+0][aRow+64] = a1.x; As[aCol+1][aRow+64] = a1.y;
        As[aCol+2][aRow+64] = a1.z; As[aCol+3][aRow+64] = a1.w;
        *(float4*)&Bs[bRow][bCol]   = b0;
        *(float4*)&Bs[bRow+8][bCol] = b1;
        __syncthreads();
        if (k0 + 16 < CC) {
            a0 = *(const float4*)(Ap + (size_t)aRow*CC + (k0+16) + aCol);
            a1 = *(const float4*)(Ap + (size_t)(aRow+64)*CC + (k0+16) + aCol);
            b0 = *(const float4*)(Bp + (size_t)(k0+16+bRow)*NCOLS + bCol);
            b1 = *(const float4*)(Bp + (size_t)(k0+16+bRow+8)*NCOLS + bCol);
        }
        #pragma unroll
        for (int kk = 0; kk < 16; kk++) {
            float ar[8], br[8];
            *(float4*)&ar[0] = *(const float4*)&As[kk][ty*8];
            *(float4*)&ar[4] = *(const float4*)&As[kk][ty*8+4];
            *(float4*)&br[0] = *(const float4*)&Bs[kk][tx*4];
            *(float4*)&br[4] = *(const float4*)&Bs[kk][64 + tx*4];
            #pragma unroll
            for (int i = 0; i < 8; i++)
                #pragma unroll
                for (int j = 0; j < 8; j++)
                    acc[i][j] = fmaf(ar[i], br[j], acc[i][j]);
        }
    }

    const int colBase = bn * 128;
    #pragma unroll
    for (int i = 0; i < 8; i++) {
        size_t r = (size_t)bm*128 + ty*8 + i;
        float4 o0, o1;
        o0.x = acc[i][0] + bias[colBase + tx*4 + 0];
        o0.y = acc[i][1] + bias[colBase + tx*4 + 1];
        o0.z = acc[i][2] + bias[colBase + tx*4 + 2];
        o0.w = acc[i][3] + bias[colBase + tx*4 + 3];
        o1.x = acc[i][4] + bias[colBase + 64 + tx*4 + 0];
        o1.y = acc[i][5] + bias[colBase + 64 + tx*4 + 1];
        o1.z = acc[i][6] + bias[colBase + 64 + tx*4 + 2];
        o1.w = acc[i][7] + bias[colBase + 64 + tx*4 + 3];
        *(float4*)(out + r*NCOLS + colBase + tx*4)      = o0;
        *(float4*)(out + r*NCOLS + colBase + 64 + tx*4) = o1;
    }
}

// ---------------- RoPE + scatter ----------------
__global__ void rope_scatter_kernel() {
    size_t i = (size_t)blockIdx.x * blockDim.x + threadIdx.x;
    if (i >= (size_t)MM*NQKV/2) return;
    size_t e = 2*i;
    int m = (int)(e / NQKV);
    int n = (int)(e % NQKV);
    float2 v = *(const float2*)(g_qkv + (size_t)m*NQKV + n);
    int which = n / CC;
    int w2 = n % CC;
    int h = w2 >> 7, d = w2 & 127;
    int bi = m / TT, t = m % TT;
    float o0 = v.x, o1 = v.y;
    if (which != 2) {
        float c = g_cos[t*64 + (d >> 1)], s = g_sin[t*64 + (d >> 1)];
        o0 = v.x*c - v.y*s;
        o1 = v.x*s + v.y*c;
    }
    float* basep = (which == 0) ? g_Q : (which == 1) ? g_K : g_V;
    *(float2*)(basep + ((size_t)(bi*HH + h)*TT + t)*DD + d) = make_float2(o0, o1);
}

// ---------------- causal flash attention (R1-proven) ----------------
#define QT_STR 68
#define ATTN_SMEM ((128*QT_STR + 128*QT_STR + 64*64) * 4)

__global__ __launch_bounds__(256, 2) void attn_kernel() {
    extern __shared__ float sm[];
    float* Qt = sm;
    float* KV = sm + 128*QT_STR;
    float* Ps = KV + 128*QT_STR;

    const int tid = threadIdx.x;
    const int tx  = tid & 15;
    const int ty  = tid >> 4;
    const int bh  = blockIdx.y;
    const int q0  = (int)(gridDim.x - 1 - blockIdx.x) * 64;

    const float* Q = g_Q + (size_t)bh*TT*DD;
    const float* K = g_K + (size_t)bh*TT*DD;
    const float* V = g_V + (size_t)bh*TT*DD;

    #pragma unroll
    for (int p = 0; p < 8; p++) {
        int idx = tid + p*256;
        int row = idx >> 5;
        int col = (idx & 31) << 2;
        float4 qv = *(const float4*)(Q + (size_t)(q0+row)*DD + col);
        Qt[(col+0)*QT_STR + row] = qv.x;
        Qt[(col+1)*QT_STR + row] = qv.y;
        Qt[(col+2)*QT_STR + row] = qv.z;
        Qt[(col+3)*QT_STR + row] = qv.w;
    }

    float m_i[4], l_i[4], O[4][8];
    #pragma unroll
    for (int ii = 0; ii < 4; ii++) {
        m_i[ii] = -1e30f; l_i[ii] = 0.f;
        #pragma unroll
        for (int dd = 0; dd < 8; dd++) O[ii][dd] = 0.f;
    }

    const int i0 = ty*4, j0 = tx*4;
    const float scale = 0.08838834764831845f;

    for (int k0 = 0; k0 <= q0; k0 += 64) {
        __syncthreads();
        #pragma unroll
        for (int p = 0; p < 8; p++) {
            int idx = tid + p*256;
            int row = idx >> 5;
            int col = (idx & 31) << 2;
            float4 kv = *(const float4*)(K + (size_t)(k0+row)*DD + col);
            KV[(col+0)*QT_STR + row] = kv.x;
            KV[(col+1)*QT_STR + row] = kv.y;
            KV[(col+2)*QT_STR + row] = kv.z;
            KV[(col+3)*QT_STR + row] = kv.w;
        }
        __syncthreads();

        float s[4][4];
        #pragma unroll
        for (int ii = 0; ii < 4; ii++)
            #pragma unroll
            for (int jj = 0; jj < 4; jj++) s[ii][jj] = 0.f;
        #pragma unroll 8
        for (int d = 0; d < 128; d++) {
            float4 q4 = *(const float4*)&Qt[d*QT_STR + i0];
            float4 k4 = *(const float4*)&KV[d*QT_STR + j0];
            float qa[4] = {q4.x, q4.y, q4.z, q4.w};
            float ka[4] = {k4.x, k4.y, k4.z, k4.w};
            #pragma unroll
            for (int ii = 0; ii < 4; ii++)
                #pragma unroll
                for (int jj = 0; jj < 4; jj++)
                    s[ii][jj] = fmaf(qa[ii], ka[jj], s[ii][jj]);
        }
        const bool diag = (k0 == q0);
        #pragma unroll
        for (int ii = 0; ii < 4; ii++)
            #pragma unroll
            for (int jj = 0; jj < 4; jj++) {
                s[ii][jj] *= scale;
                if (diag && (k0 + j0 + jj > q0 + i0 + ii)) s[ii][jj] = -1e30f;
            }

        #pragma unroll
        for (int ii = 0; ii < 4; ii++) {
            float mx = fmaxf(fmaxf(s[ii][0], s[ii][1]), fmaxf(s[ii][2], s[ii][3]));
            #pragma unroll
            for (int off = 8; off > 0; off >>= 1)
                mx = fmaxf(mx, __shfl_xor_sync(0xffffffffu, mx, off, 16));
            float mnew = fmaxf(m_i[ii], mx);
            float p0 = __expf(s[ii][0] - mnew);
            float p1 = __expf(s[ii][1] - mnew);
            float p2 = __expf(s[ii][2] - mnew);
            float p3 = __expf(s[ii][3] - mnew);
            float rs = p0 + p1 + p2 + p3;
            #pragma unroll
            for (int off = 8; off > 0; off >>= 1)
                rs += __shfl_xor_sync(0xffffffffu, rs, off, 16);
            float alpha = __expf(m_i[ii] - mnew);
            l_i[ii] = l_i[ii]*alpha + rs;
            m_i[ii] = mnew;
            #pragma unroll
            for (int dd = 0; dd < 8; dd++) O[ii][dd] *= alpha;
            *(float4*)&Ps[(i0+ii)*64 + j0] = make_float4(p0, p1, p2, p3);
        }
        __syncthreads();

        #pragma unroll
        for (int p = 0; p < 8; p++) {
            int idx = tid + p*256;
            int row = idx >> 5;
            int col = (idx & 31) << 2;
            *(float4*)&KV[row*128 + col] =
                *(const float4*)(V + (size_t)(k0+row)*DD + col);
        }
        __syncthreads();

        #pragma unroll 2
        for (int j = 0; j < 64; j++) {
            float4 v0 = *(const float4*)&KV[j*128 + tx*4];
            float4 v1 = *(const float4*)&KV[j*128 + 64 + tx*4];
            #pragma unroll
            for (int ii = 0; ii < 4; ii++) {
                float p = Ps[(i0+ii)*64 + j];
                O[ii][0] = fmaf(p, v0.x, O[ii][0]);
                O[ii][1] = fmaf(p, v0.y, O[ii][1]);
                O[ii][2] = fmaf(p, v0.z, O[ii][2]);
                O[ii][3] = fmaf(p, v0.w, O[ii][3]);
                O[ii][4] = fmaf(p, v1.x, O[ii][4]);
                O[ii][5] = fmaf(p, v1.y, O[ii][5]);
                O[ii][6] = fmaf(p, v1.z, O[ii][6]);
                O[ii][7] = fmaf(p, v1.w, O[ii][7]);
            }
        }
    }

    const int b = bh / HH, h = bh % HH;
    #pragma unroll
    for (int ii = 0; ii < 4; ii++) {
        float inv = 1.0f / l_i[ii];
        int q = q0 + i0 + ii;
        float* dst = g_attn + ((size_t)(b*TT + q))*CC + h*DD;
        *(float4*)(dst + tx*4) =
            make_float4(O[ii][0]*inv, O[ii][1]*inv, O[ii][2]*inv, O[ii][3]*inv);
        *(float4*)(dst + 64 + tx*4) =
            make_float4(O[ii][4]*inv, O[ii][5]*inv, O[ii][6]*inv, O[ii][7]*inv);
    }
}

// ---------------- launcher (NO __device__ symbols as arguments!) ----------------
extern "C" void kernel_launch(void* const* d_in, const int* in_sizes, int n_in,
                              void* d_out, int out_size) {
    const float* x      = (const float*)d_in[0];
    const float* W_attn = (const float*)d_in[1];
    const float* b_attn = (const float*)d_in[2];
    const float* W_proj = (const float*)d_in[3];
    const float* b_proj = (const float*)d_in[4];
    float* out = (float*)d_out;

    cudaFuncSetAttribute(gemm_mma<0>, cudaFuncAttributeMaxDynamicSharedMemorySize, GEMM_SMEM);
    cudaFuncSetAttribute(gemm_mma<1>, cudaFuncAttributeMaxDynamicSharedMemorySize, GEMM_SMEM);
    cudaFuncSetAttribute(attn_kernel, cudaFuncAttributeMaxDynamicSharedMemorySize, ATTN_SMEM);

    reset_flags_kernel<<<1, 32>>>();
    rope_init_kernel<<<(TT*(DD/2) + 255)/256, 256>>>();
    conv_split_kernel<0><<<(MM*CC/2 + 255)/256, 256>>>(x);
    conv_wT_kernel<0><<<dim3(NQKV/32, CC/32), 256>>>(W_attn);
    conv_wT_kernel<1><<<dim3(CC/32,   CC/32), 256>>>(W_proj);

    // QKV: mma, spot-check, conditional fp32 fallback
    gemm_mma<0><<<(MM/128)*(NQKV/128), 256, GEMM_SMEM>>>(b_attn, nullptr);
    check_kernel<0><<<8, 256>>>(x, W_attn, b_attn, nullptr);
    gemm_fb<0><<<dim3(NQKV/128, MM/128), 256>>>(x, W_attn, b_attn, nullptr);

    rope_scatter_kernel<<<(int)(((size_t)MM*NQKV/2 + 255)/256), 256>>>();

    attn_kernel<<<dim3(TT/64, BB*HH), 256, ATTN_SMEM>>>();

    conv_split_kernel<1><<<(MM*CC/2 + 255)/256, 256>>>(nullptr);

    // proj: mma, spot-check, conditional fp32 fallback
    gemm_mma<1><<<(MM/128)*(CC/128), 256, GEMM_SMEM>>>(b_proj, out);
    check_kernel<1><<<8, 256>>>(nullptr, W_proj, b_proj, out);
    gemm_fb<1><<<dim3(CC/128, MM/128), 256>>>(nullptr, W_proj, b_proj, out);
}

// round 10
// speedup vs baseline: 1.9108x; 1.8235x over previous
#include <cuda_runtime.h>
#include <cuda_bf16.h>
#include <math.h>
#include <cstdint>

#define BB 2
#define TT 2048
#define CC 2048
#define HH 16
#define DD 128
#define MM (BB*TT)        // 4096
#define NQKV (3*CC)       // 6144

// ---------------- scratch (__device__ globals; NEVER passed as host-side kernel args) ----------------
static __device__ __align__(256) float g_qkv[(size_t)MM*NQKV];
static __device__ __align__(256) float g_cos[TT*(DD/2)];
static __device__ __align__(256) float g_sin[TT*(DD/2)];
static __device__ __align__(256) __nv_bfloat16 g_Xh [(size_t)MM*CC],   g_Xl [(size_t)MM*CC];
static __device__ __align__(256) __nv_bfloat16 g_Wqh[(size_t)NQKV*CC], g_Wql[(size_t)NQKV*CC];
static __device__ __align__(256) __nv_bfloat16 g_Wph[(size_t)CC*CC],   g_Wpl[(size_t)CC*CC];
static __device__ __align__(256) __nv_bfloat16 g_AOh[(size_t)MM*CC],   g_AOl[(size_t)MM*CC];
// bf16 hi/lo Q,K,V in [b*H+h][t][d]
static __device__ __align__(256) __nv_bfloat16 g_Qh[(size_t)BB*HH*TT*DD], g_Ql[(size_t)BB*HH*TT*DD];
static __device__ __align__(256) __nv_bfloat16 g_Kh[(size_t)BB*HH*TT*DD], g_Kl[(size_t)BB*HH*TT*DD];
static __device__ __align__(256) __nv_bfloat16 g_Vh[(size_t)BB*HH*TT*DD], g_Vl[(size_t)BB*HH*TT*DD];

__device__ __forceinline__ void mma16816(float* c, const uint32_t* a, const uint32_t* b){
    asm volatile("mma.sync.aligned.m16n8k16.row.col.f32.bf16.bf16.f32 "
                 "{%0,%1,%2,%3}, {%4,%5,%6,%7}, {%8,%9}, {%0,%1,%2,%3};"
                 : "+f"(c[0]), "+f"(c[1]), "+f"(c[2]), "+f"(c[3])
                 : "r"(a[0]), "r"(a[1]), "r"(a[2]), "r"(a[3]), "r"(b[0]), "r"(b[1]));
}
__device__ __forceinline__ uint32_t pack2(__nv_bfloat16 a, __nv_bfloat16 b){
    return ((uint32_t)*(uint16_t*)&b << 16) | *(uint16_t*)&a;
}

// ---------------- init ----------------
__global__ void rope_init_kernel() {
    int idx = blockIdx.x * blockDim.x + threadIdx.x;
    if (idx >= TT*(DD/2)) return;
    int t = idx / (DD/2);
    int i = idx - t*(DD/2);
    float inv = powf(10000.0f, -(float)(2*i) / (float)DD);
    float ang = (float)t * inv;
    g_cos[idx] = cosf(ang);
    g_sin[idx] = sinf(ang);
}

// ---------------- conversions ----------------
__global__ void conv_split_kernel(const float* __restrict__ xin) {
    int i = blockIdx.x * blockDim.x + threadIdx.x;
    if (i >= MM*CC/2) return;
    float2 v = ((const float2*)xin)[i];
    __nv_bfloat16 h0 = __float2bfloat16(v.x), h1 = __float2bfloat16(v.y);
    __nv_bfloat16 l0 = __float2bfloat16(v.x - __bfloat162float(h0));
    __nv_bfloat16 l1 = __float2bfloat16(v.y - __bfloat162float(h1));
    ((__nv_bfloat162*)g_Xh)[i] = __halves2bfloat162(h0, h1);
    ((__nv_bfloat162*)g_Xl)[i] = __halves2bfloat162(l0, l1);
}

template<int SEL>
__global__ void conv_wT_kernel(const float* __restrict__ W) {
    constexpr int N = (SEL == 0) ? NQKV : CC;
    __nv_bfloat16* oh = (SEL == 0) ? g_Wqh : g_Wph;
    __nv_bfloat16* ol = (SEL == 0) ? g_Wql : g_Wpl;
    __shared__ float t[32][33];
    int k0 = blockIdx.y * 32, n0 = blockIdx.x * 32;
    int tid = threadIdx.x;
    #pragma unroll
    for (int r = 0; r < 4; r++) {
        int kk = (tid >> 5) + r*8, nn = tid & 31;
        t[kk][nn] = W[(size_t)(k0+kk)*N + n0 + nn];
    }
    __syncthreads();
    int nn = tid >> 3, ks = (tid & 7) * 4;
    size_t base = (size_t)(n0+nn)*CC + k0 + ks;
    float v[4];
    #pragma unroll
    for (int j = 0; j < 4; j++) v[j] = t[ks+j][nn];
    __nv_bfloat16 h[4], l[4];
    #pragma unroll
    for (int j = 0; j < 4; j++) {
        h[j] = __float2bfloat16(v[j]);
        l[j] = __float2bfloat16(v[j] - __bfloat162float(h[j]));
    }
    *(__nv_bfloat162*)(oh + base)     = __halves2bfloat162(h[0], h[1]);
    *(__nv_bfloat162*)(oh + base + 2) = __halves2bfloat162(h[2], h[3]);
    *(__nv_bfloat162*)(ol + base)     = __halves2bfloat162(l[0], l[1]);
    *(__nv_bfloat162*)(ol + base + 2) = __halves2bfloat162(l[2], l[3]);
}

// ---------------- verified bf16x3 mma GEMM (R7, unchanged) ----------------
#define TILE_B 10240
#define BUF_B  (4*TILE_B)
#define GEMM_SMEM (2*BUF_B)

template<int PHASE>
__global__ __launch_bounds__(256, 1)
void gemm_mma(const float* __restrict__ bias, float* __restrict__ out_p)
{
    constexpr int Ntot = (PHASE == 0) ? NQKV : CC;
    const __nv_bfloat16* __restrict__ pAh = (PHASE == 0) ? g_Xh  : g_AOh;
    const __nv_bfloat16* __restrict__ pAl = (PHASE == 0) ? g_Xl  : g_AOl;
    const __nv_bfloat16* __restrict__ pBh = (PHASE == 0) ? g_Wqh : g_Wph;
    const __nv_bfloat16* __restrict__ pBl = (PHASE == 0) ? g_Wql : g_Wpl;
    float* __restrict__ out = (PHASE == 0) ? g_qkv : out_p;

    extern __shared__ char smraw[];
    const int tid  = threadIdx.x;
    const int lane = tid & 31;
    const int wid  = tid >> 5;
    const int wm   = wid & 3;
    const int wn   = wid >> 2;

    const int nT = Ntot / 128;
    int id  = blockIdx.x;
    int gsz = 8 * nT;
    int bm  = (id / gsz) * 8 + (id % gsz) % 8;
    int bn  = (id % gsz) / 8;
    const int m0 = bm * 128, n0 = bn * 128;

    const int r0 = tid >> 2, sg = tid & 3;
    const size_t aoff = (size_t)(m0 + r0)*CC + sg*8;
    const size_t boff = (size_t)(n0 + r0)*CC + sg*8;
    const uint32_t so = (uint32_t)(r0*80 + sg*16);

    float4 sAh0, sAh1, sAl0, sAl1, sBh0, sBh1, sBl0, sBl1;
    auto fetch = [&](int s) {
        size_t ks = (size_t)s*32;
        sAh0 = *(const float4*)(pAh + aoff + ks);
        sAh1 = *(const float4*)(pAh + aoff + (size_t)64*CC + ks);
        sAl0 = *(const float4*)(pAl + aoff + ks);
        sAl1 = *(const float4*)(pAl + aoff + (size_t)64*CC + ks);
        sBh0 = *(const float4*)(pBh + boff + ks);
        sBh1 = *(const float4*)(pBh + boff + (size_t)64*CC + ks);
        sBl0 = *(const float4*)(pBl + boff + ks);
        sBl1 = *(const float4*)(pBl + boff + (size_t)64*CC + ks);
    };
    auto deposit = [&](int b) {
        char* base = smraw + b*BUF_B;
        *(float4*)(base +            so) = sAh0;  *(float4*)(base +            so + 5120) = sAh1;
        *(float4*)(base +   TILE_B + so) = sAl0;  *(float4*)(base +   TILE_B + so + 5120) = sAl1;
        *(float4*)(base + 2*TILE_B + so) = sBh0;  *(float4*)(base + 2*TILE_B + so + 5120) = sBh1;
        *(float4*)(base + 3*TILE_B + so) = sBl0;  *(float4*)(base + 3*TILE_B + so + 5120) = sBl1;
    };

    float acc[2][8][4];
    #pragma unroll
    for (int mt = 0; mt < 2; mt++)
        #pragma unroll
        for (int nt = 0; nt < 8; nt++)
            #pragma unroll
            for (int q = 0; q < 4; q++) acc[mt][nt][q] = 0.f;

    const int NS = CC / 32;
    fetch(0);
    for (int s = 0; s < NS; s++) {
        int buf = s & 1;
        deposit(buf);
        __syncthreads();
        if (s + 1 < NS) fetch(s + 1);

        const char* cAh = smraw + buf*BUF_B;
        const char* cAl = cAh + TILE_B;
        const char* cBh = cAh + 2*TILE_B;
        const char* cBl = cAh + 3*TILE_B;

        #pragma unroll
        for (int kc = 0; kc < 2; kc++) {
            uint32_t ah[2][4], al[2][4], bh[8][2], bl[8][2];
            #pragma unroll
            for (int mt = 0; mt < 2; mt++) {
                uint32_t fr = (uint32_t)((wm*32 + mt*16 + (lane>>2))*80 + kc*32 + (lane&3)*4);
                ah[mt][0] = *(const uint32_t*)(cAh + fr);
                ah[mt][1] = *(const uint32_t*)(cAh + fr + 8*80);
                ah[mt][2] = *(const uint32_t*)(cAh + fr + 16);
                ah[mt][3] = *(const uint32_t*)(cAh + fr + 8*80 + 16);
                al[mt][0] = *(const uint32_t*)(cAl + fr);
                al[mt][1] = *(const uint32_t*)(cAl + fr + 8*80);
                al[mt][2] = *(const uint32_t*)(cAl + fr + 16);
                al[mt][3] = *(const uint32_t*)(cAl + fr + 8*80 + 16);
            }
            #pragma unroll
            for (int nt = 0; nt < 8; nt++) {
                uint32_t fb = (uint32_t)((wn*64 + nt*8 + (lane>>2))*80 + kc*32 + (lane&3)*4);
                bh[nt][0] = *(const uint32_t*)(cBh + fb);
                bh[nt][1] = *(const uint32_t*)(cBh + fb + 16);
                bl[nt][0] = *(const uint32_t*)(cBl + fb);
                bl[nt][1] = *(const uint32_t*)(cBl + fb + 16);
            }
            #pragma unroll
            for (int mt = 0; mt < 2; mt++)
                #pragma unroll
                for (int nt = 0; nt < 8; nt++) {
                    mma16816(acc[mt][nt], ah[mt], bh[nt]);
                    mma16816(acc[mt][nt], ah[mt], bl[nt]);
                    mma16816(acc[mt][nt], al[mt], bh[nt]);
                }
        }
        __syncthreads();
    }

    const int gid = lane >> 2, tig = lane & 3;
    #pragma unroll
    for (int mt = 0; mt < 2; mt++) {
        int m = m0 + wm*32 + mt*16 + gid;
        #pragma unroll
        for (int nt = 0; nt < 8; nt++) {
            int n = n0 + wn*64 + nt*8 + tig*2;
            float bv0 = bias[n], bv1 = bias[n+1];
            *(float2*)(out + (size_t)m*Ntot + n)     = make_float2(acc[mt][nt][0] + bv0, acc[mt][nt][1] + bv1);
            *(float2*)(out + (size_t)(m+8)*Ntot + n) = make_float2(acc[mt][nt][2] + bv0, acc[mt][nt][3] + bv1);
        }
    }
}

// ---------------- RoPE + scatter -> bf16 hi/lo Q,K,V ----------------
__global__ void rope_scatter_kernel() {
    size_t i = (size_t)blockIdx.x * blockDim.x + threadIdx.x;
    if (i >= (size_t)MM*NQKV/2) return;
    size_t e = 2*i;
    int m = (int)(e / NQKV);
    int n = (int)(e % NQKV);
    float2 v = *(const float2*)(g_qkv + (size_t)m*NQKV + n);
    int which = n / CC;
    int w2 = n % CC;
    int h = w2 >> 7, d = w2 & 127;
    int bi = m / TT, t = m % TT;
    float o0 = v.x, o1 = v.y;
    if (which != 2) {
        float c = g_cos[t*64 + (d >> 1)], s = g_sin[t*64 + (d >> 1)];
        o0 = v.x*c - v.y*s;
        o1 = v.x*s + v.y*c;
    }
    __nv_bfloat16 h0 = __float2bfloat16(o0), h1 = __float2bfloat16(o1);
    __nv_bfloat16 l0 = __float2bfloat16(o0 - __bfloat162float(h0));
    __nv_bfloat16 l1 = __float2bfloat16(o1 - __bfloat162float(h1));
    __nv_bfloat16* ph = (which == 0) ? g_Qh : (which == 1) ? g_Kh : g_Vh;
    __nv_bfloat16* pl = (which == 0) ? g_Ql : (which == 1) ? g_Kl : g_Vl;
    size_t off = ((size_t)(bi*HH + h)*TT + t)*DD + d;
    *(__nv_bfloat162*)(ph + off) = __halves2bfloat162(h0, h1);
    *(__nv_bfloat162*)(pl + off) = __halves2bfloat162(l0, l1);
}

// ---------------- mma.sync flash attention: CTA 128q, warp 16q x 64k tiles ----------------
#define AQ_STR 272        // Q/K smem row stride (256B data + 16 pad)
#define AV_STR 144        // Vt smem row stride (128B data + 16 pad)
#define SM_QH 0
#define SM_QL 34816
#define SM_KH 69632
#define SM_KL 87040
#define SM_VH 104448
#define SM_VL 122880
#define ATTN_SMEM 141312

__global__ __launch_bounds__(256, 1) void attn_mma_kernel() {
    extern __shared__ char smc[];
    const int tid  = threadIdx.x;
    const int lane = tid & 31;
    const int w    = tid >> 5;
    const int r1   = lane >> 2;      // fragment row 0..7
    const int c4   = lane & 3;       // fragment col group
    const int bh   = blockIdx.y;
    const int q0   = (int)(gridDim.x - 1 - blockIdx.x) * 128;   // heavy-first

    const __nv_bfloat16* Qh = g_Qh + (size_t)bh*TT*DD;
    const __nv_bfloat16* Ql = g_Ql + (size_t)bh*TT*DD;
    const __nv_bfloat16* Kh = g_Kh + (size_t)bh*TT*DD;
    const __nv_bfloat16* Kl = g_Kl + (size_t)bh*TT*DD;
    const __nv_bfloat16* Vh = g_Vh + (size_t)bh*TT*DD;
    const __nv_bfloat16* Vl = g_Vl + (size_t)bh*TT*DD;

    // load Q tile (128 x 128), hi+lo
    #pragma unroll
    for (int p = 0; p < 8; p++) {
        int idx = tid + p*256;
        int row = idx >> 4, c16 = idx & 15;
        *(float4*)(smc + SM_QH + row*AQ_STR + c16*16) = *(const float4*)(Qh + (size_t)(q0+row)*DD + c16*8);
        *(float4*)(smc + SM_QL + row*AQ_STR + c16*16) = *(const float4*)(Ql + (size_t)(q0+row)*DD + c16*8);
    }

    const int qrow1 = q0 + w*16 + r1;
    const int qrow2 = qrow1 + 8;
    float m1 = -1e30f, m2 = -1e30f, l1 = 0.f, l2 = 0.f;
    float O[16][4];
    #pragma unroll
    for (int vt = 0; vt < 16; vt++)
        #pragma unroll
        for (int q = 0; q < 4; q++) O[vt][q] = 0.f;

    const float scale = 0.08838834764831845f;
    const int ktmax = q0/64 + 1;

    for (int kt = 0; kt <= ktmax; kt++) {
        __syncthreads();   // previous iteration's mma reads done
        // K tile 64x128 hi/lo
        #pragma unroll
        for (int p = 0; p < 4; p++) {
            int idx = tid + p*256;
            int row = idx >> 4, c16 = idx & 15;
            *(float4*)(smc + SM_KH + row*AQ_STR + c16*16) = *(const float4*)(Kh + (size_t)(kt*64+row)*DD + c16*8);
            *(float4*)(smc + SM_KL + row*AQ_STR + c16*16) = *(const float4*)(Kl + (size_t)(kt*64+row)*DD + c16*8);
        }
        // V tile transposed: Vt[d][key], hi/lo
        #pragma unroll
        for (int p = 0; p < 16; p++) {
            int idx = tid + p*256;
            int t = idx >> 6, j = idx & 63;   // j = d-pair
            uint32_t vh = *(const uint32_t*)(Vh + (size_t)(kt*64+t)*DD + j*2);
            uint32_t vl = *(const uint32_t*)(Vl + (size_t)(kt*64+t)*DD + j*2);
            *(uint16_t*)(smc + SM_VH + (2*j  )*AV_STR + t*2) = (uint16_t)(vh & 0xffff);
            *(uint16_t*)(smc + SM_VH + (2*j+1)*AV_STR + t*2) = (uint16_t)(vh >> 16);
            *(uint16_t*)(smc + SM_VL + (2*j  )*AV_STR + t*2) = (uint16_t)(vl & 0xffff);
            *(uint16_t*)(smc + SM_VL + (2*j+1)*AV_STR + t*2) = (uint16_t)(vl >> 16);
        }
        __syncthreads();

        // S = Q K^T  (bf16x3)
        float S[8][4];
        #pragma unroll
        for (int nt = 0; nt < 8; nt++)
            #pragma unroll
            for (int q = 0; q < 4; q++) S[nt][q] = 0.f;
        #pragma unroll
        for (int kc = 0; kc < 8; kc++) {
            uint32_t ah[4], al[4];
            uint32_t fr = (uint32_t)((w*16 + r1)*AQ_STR + kc*32 + c4*4);
            ah[0] = *(const uint32_t*)(smc + SM_QH + fr);
            ah[1] = *(const uint32_t*)(smc + SM_QH + fr + 8*AQ_STR);
            ah[2] = *(const uint32_t*)(smc + SM_QH + fr + 16);
            ah[3] = *(const uint32_t*)(smc + SM_QH + fr + 8*AQ_STR + 16);
            al[0] = *(const uint32_t*)(smc + SM_QL + fr);
            al[1] = *(const uint32_t*)(smc + SM_QL + fr + 8*AQ_STR);
            al[2] = *(const uint32_t*)(smc + SM_QL + fr + 16);
            al[3] = *(const uint32_t*)(smc + SM_QL + fr + 8*AQ_STR + 16);
            #pragma unroll
            for (int nt = 0; nt < 8; nt++) {
                uint32_t fb = (uint32_t)((nt*8 + r1)*AQ_STR + kc*32 + c4*4);
                uint32_t bh[2], bl[2];
                bh[0] = *(const uint32_t*)(smc + SM_KH + fb);
                bh[1] = *(const uint32_t*)(smc + SM_KH + fb + 16);
                bl[0] = *(const uint32_t*)(smc + SM_KL + fb);
                bl[1] = *(const uint32_t*)(smc + SM_KL + fb + 16);
                mma16816(S[nt], ah, bh);
                mma16816(S[nt], ah, bl);
                mma16816(S[nt], al, bh);
            }
        }

        // scale + causal mask + row max
        float mx1 = -1e30f, mx2 = -1e30f;
        #pragma unroll
        for (int nt = 0; nt < 8; nt++) {
            int col0 = kt*64 + nt*8 + 2*c4;
            S[nt][0] = (col0     <= qrow1) ? S[nt][0]*scale : -1e30f;
            S[nt][1] = (col0 + 1 <= qrow1) ? S[nt][1]*scale : -1e30f;
            S[nt][2] = (col0     <= qrow2) ? S[nt][2]*scale : -1e30f;
            S[nt][3] = (col0 + 1 <= qrow2) ? S[nt][3]*scale : -1e30f;
            mx1 = fmaxf(mx1, fmaxf(S[nt][0], S[nt][1]));
            mx2 = fmaxf(mx2, fmaxf(S[nt][2], S[nt][3]));
        }
        #pragma unroll
        for (int off = 1; off <= 2; off <<= 1) {
            mx1 = fmaxf(mx1, __shfl_xor_sync(0xffffffffu, mx1, off));
            mx2 = fmaxf(mx2, __shfl_xor_sync(0xffffffffu, mx2, off));
        }
        float mn1 = fmaxf(m1, mx1), mn2 = fmaxf(m2, mx2);
        float al1 = __expf(m1 - mn1), al2 = __expf(m2 - mn2);
        m1 = mn1; m2 = mn2;

        // P = exp(S - m), split hi/lo, accumulate row sums
        uint32_t ph1[8], ph2[8], pl1[8], pl2[8];
        float rs1 = 0.f, rs2 = 0.f;
        #pragma unroll
        for (int nt = 0; nt < 8; nt++) {
            float p00 = __expf(S[nt][0] - mn1), p01 = __expf(S[nt][1] - mn1);
            float p10 = __expf(S[nt][2] - mn2), p11 = __expf(S[nt][3] - mn2);
            rs1 += p00 + p01; rs2 += p10 + p11;
            __nv_bfloat16 h00 = __float2bfloat16(p00), h01 = __float2bfloat16(p01);
            __nv_bfloat16 h10 = __float2bfloat16(p10), h11 = __float2bfloat16(p11);
            ph1[nt] = pack2(h00, h01);
            ph2[nt] = pack2(h10, h11);
            pl1[nt] = pack2(__float2bfloat16(p00 - __bfloat162float(h00)),
                            __float2bfloat16(p01 - __bfloat162float(h01)));
            pl2[nt] = pack2(__float2bfloat16(p10 - __bfloat162float(h10)),
                            __float2bfloat16(p11 - __bfloat162float(h11)));
        }
        #pragma unroll
        for (int off = 1; off <= 2; off <<= 1) {
            rs1 += __shfl_xor_sync(0xffffffffu, rs1, off);
            rs2 += __shfl_xor_sync(0xffffffffu, rs2, off);
        }
        l1 = l1*al1 + rs1;
        l2 = l2*al2 + rs2;
        #pragma unroll
        for (int vt = 0; vt < 16; vt++) {
            O[vt][0] *= al1; O[vt][1] *= al1;
            O[vt][2] *= al2; O[vt][3] *= al2;
        }

        // O += P V   (bf16x3; P frags direct from registers)
        #pragma unroll
        for (int kc = 0; kc < 4; kc++) {
            uint32_t pa[4] = { ph1[2*kc], ph2[2*kc], ph1[2*kc+1], ph2[2*kc+1] };
            uint32_t pb[4] = { pl1[2*kc], pl2[2*kc], pl1[2*kc+1], pl2[2*kc+1] };
            #pragma unroll
            for (int vt = 0; vt < 16; vt++) {
                uint32_t fb = (uint32_t)((vt*8 + r1)*AV_STR + kc*32 + c4*4);
                uint32_t bh[2], bl[2];
                bh[0] = *(const uint32_t*)(smc + SM_VH + fb);
                bh[1] = *(const uint32_t*)(smc + SM_VH + fb + 16);
                bl[0] = *(const uint32_t*)(smc + SM_VL + fb);
                bl[1] = *(const uint32_t*)(smc + SM_VL + fb + 16);
                mma16816(O[vt], pa, bh);
                mma16816(O[vt], pa, bl);
                mma16816(O[vt], pb, bh);
            }
        }
    }

    // epilogue: normalize, split hi/lo, write g_AOh/g_AOl
    const int b = bh >> 4, h = bh & 15;
    const float i1 = 1.0f / l1, i2 = 1.0f / l2;
    const size_t mrow1 = (size_t)(b*TT + qrow1) * CC;
    const size_t mrow2 = (size_t)(b*TT + qrow2) * CC;
    #pragma unroll
    for (int vt = 0; vt < 16; vt++) {
        int col = h*DD + vt*8 + 2*c4;
        float o00 = O[vt][0]*i1, o01 = O[vt][1]*i1;
        float o10 = O[vt][2]*i2, o11 = O[vt][3]*i2;
        __nv_bfloat16 h00 = __float2bfloat16(o00), h01 = __float2bfloat16(o01);
        __nv_bfloat16 h10 = __float2bfloat16(o10), h11 = __float2bfloat16(o11);
        *(__nv_bfloat162*)(g_AOh + mrow1 + col) = __halves2bfloat162(h00, h01);
        *(__nv_bfloat162*)(g_AOh + mrow2 + col) = __halves2bfloat162(h10, h11);
        *(__nv_bfloat162*)(g_AOl + mrow1 + col) = __halves2bfloat162(
            __float2bfloat16(o00 - __bfloat162float(h00)), __float2bfloat16(o01 - __bfloat162float(h01)));
        *(__nv_bfloat162*)(g_AOl + mrow2 + col) = __halves2bfloat162(
            __float2bfloat16(o10 - __bfloat162float(h10)), __float2bfloat16(o11 - __bfloat162float(h11)));
    }
}

// ---------------- launcher (no __device__ symbols as host-side args) ----------------
extern "C" void kernel_launch(void* const* d_in, const int* in_sizes, int n_in,
                              void* d_out, int out_size) {
    const float* x      = (const float*)d_in[0];
    const float* W_attn = (const float*)d_in[1];
    const float* b_attn = (const float*)d_in[2];
    const float* W_proj = (const float*)d_in[3];
    const float* b_proj = (const float*)d_in[4];
    float* out = (float*)d_out;

    cudaFuncSetAttribute(gemm_mma<0>, cudaFuncAttributeMaxDynamicSharedMemorySize, GEMM_SMEM);
    cudaFuncSetAttribute(gemm_mma<1>, cudaFuncAttributeMaxDynamicSharedMemorySize, GEMM_SMEM);
    cudaFuncSetAttribute(attn_mma_kernel, cudaFuncAttributeMaxDynamicSharedMemorySize, ATTN_SMEM);

    rope_init_kernel<<<(TT*(DD/2) + 255)/256, 256>>>();
    conv_split_kernel<<<(MM*CC/2 + 255)/256, 256>>>(x);
    conv_wT_kernel<0><<<dim3(NQKV/32, CC/32), 256>>>(W_attn);
    conv_wT_kernel<1><<<dim3(CC/32,   CC/32), 256>>>(W_proj);

    gemm_mma<0><<<(MM/128)*(NQKV/128), 256, GEMM_SMEM>>>(b_attn, nullptr);

    rope_scatter_kernel<<<(int)(((size_t)MM*NQKV/2 + 255)/256), 256>>>();

    attn_mma_kernel<<<dim3(TT/128, BB*HH), 256, ATTN_SMEM>>>();

    gemm_mma<1><<<(MM/128)*(CC/128), 256, GEMM_SMEM>>>(b_proj, out);
}

// round 13
// speedup vs baseline: 2.0950x; 1.0964x over previous
#include <cuda_runtime.h>
#include <cuda_bf16.h>
#include <math.h>
#include <cstdint>

#define BB 2
#define TT 2048
#define CC 2048
#define HH 16
#define DD 128
#define MM (BB*TT)        // 4096
#define NQKV (3*CC)       // 6144

// ---------------- scratch (__device__ globals; NEVER passed as host-side kernel args) ----------------
static __device__ __align__(256) float g_qkv[(size_t)MM*NQKV];
static __device__ __align__(256) float g_cos[TT*(DD/2)];
static __device__ __align__(256) float g_sin[TT*(DD/2)];
static __device__ __align__(256) __nv_bfloat16 g_Xh [(size_t)MM*CC],   g_Xl [(size_t)MM*CC];
static __device__ __align__(256) __nv_bfloat16 g_Wqh[(size_t)NQKV*CC], g_Wql[(size_t)NQKV*CC];
static __device__ __align__(256) __nv_bfloat16 g_Wph[(size_t)CC*CC],   g_Wpl[(size_t)CC*CC];
static __device__ __align__(256) __nv_bfloat16 g_AOh[(size_t)MM*CC],   g_AOl[(size_t)MM*CC];
// bf16 hi/lo Q,K,V in [b*H+h][t][d]; Vt transposed [b*H+h][d][t]
static __device__ __align__(256) __nv_bfloat16 g_Qh[(size_t)BB*HH*TT*DD], g_Ql[(size_t)BB*HH*TT*DD];
static __device__ __align__(256) __nv_bfloat16 g_Kh[(size_t)BB*HH*TT*DD], g_Kl[(size_t)BB*HH*TT*DD];
static __device__ __align__(256) __nv_bfloat16 g_Vh[(size_t)BB*HH*TT*DD], g_Vl[(size_t)BB*HH*TT*DD];
static __device__ __align__(256) __nv_bfloat16 g_Vth[(size_t)BB*HH*TT*DD], g_Vtl[(size_t)BB*HH*TT*DD];

__device__ __forceinline__ void mma16816(float* c, const uint32_t* a, const uint32_t* b){
    asm volatile("mma.sync.aligned.m16n8k16.row.col.f32.bf16.bf16.f32 "
                 "{%0,%1,%2,%3}, {%4,%5,%6,%7}, {%8,%9}, {%0,%1,%2,%3};"
                 : "+f"(c[0]), "+f"(c[1]), "+f"(c[2]), "+f"(c[3])
                 : "r"(a[0]), "r"(a[1]), "r"(a[2]), "r"(a[3]), "r"(b[0]), "r"(b[1]));
}
__device__ __forceinline__ uint32_t pack2(__nv_bfloat16 a, __nv_bfloat16 b){
    return ((uint32_t)*(uint16_t*)&b << 16) | *(uint16_t*)&a;
}
__device__ __forceinline__ uint32_t smem_u32(const void* p){
    uint32_t a;
    asm("{ .reg .u64 t; cvta.to.shared.u64 t, %1; cvt.u32.u64 %0, t; }" : "=r"(a) : "l"(p));
    return a;
}
__device__ __forceinline__ void cp16(uint32_t dst, const void* src){
    asm volatile("cp.async.cg.shared.global [%0], [%1], 16;" :: "r"(dst), "l"(src));
}

// ---------------- init ----------------
__global__ void rope_init_kernel() {
    int idx = blockIdx.x * blockDim.x + threadIdx.x;
    if (idx >= TT*(DD/2)) return;
    int t = idx / (DD/2);
    int i = idx - t*(DD/2);
    float inv = powf(10000.0f, -(float)(2*i) / (float)DD);
    float ang = (float)t * inv;
    g_cos[idx] = cosf(ang);
    g_sin[idx] = sinf(ang);
}

// ---------------- conversions ----------------
__global__ void conv_split_kernel(const float* __restrict__ xin) {
    int i = blockIdx.x * blockDim.x + threadIdx.x;
    if (i >= MM*CC/2) return;
    float2 v = ((const float2*)xin)[i];
    __nv_bfloat16 h0 = __float2bfloat16(v.x), h1 = __float2bfloat16(v.y);
    __nv_bfloat16 l0 = __float2bfloat16(v.x - __bfloat162float(h0));
    __nv_bfloat16 l1 = __float2bfloat16(v.y - __bfloat162float(h1));
    ((__nv_bfloat162*)g_Xh)[i] = __halves2bfloat162(h0, h1);
    ((__nv_bfloat162*)g_Xl)[i] = __halves2bfloat162(l0, l1);
}

template<int SEL>
__global__ void conv_wT_kernel(const float* __restrict__ W) {
    constexpr int N = (SEL == 0) ? NQKV : CC;
    __nv_bfloat16* oh = (SEL == 0) ? g_Wqh : g_Wph;
    __nv_bfloat16* ol = (SEL == 0) ? g_Wql : g_Wpl;
    __shared__ float t[32][33];
    int k0 = blockIdx.y * 32, n0 = blockIdx.x * 32;
    int tid = threadIdx.x;
    #pragma unroll
    for (int r = 0; r < 4; r++) {
        int kk = (tid >> 5) + r*8, nn = tid & 31;
        t[kk][nn] = W[(size_t)(k0+kk)*N + n0 + nn];
    }
    __syncthreads();
    int nn = tid >> 3, ks = (tid & 7) * 4;
    size_t base = (size_t)(n0+nn)*CC + k0 + ks;
    float v[4];
    #pragma unroll
    for (int j = 0; j < 4; j++) v[j] = t[ks+j][nn];
    __nv_bfloat16 h[4], l[4];
    #pragma unroll
    for (int j = 0; j < 4; j++) {
        h[j] = __float2bfloat16(v[j]);
        l[j] = __float2bfloat16(v[j] - __bfloat162float(h[j]));
    }
    *(__nv_bfloat162*)(oh + base)     = __halves2bfloat162(h[0], h[1]);
    *(__nv_bfloat162*)(oh + base + 2) = __halves2bfloat162(h[2], h[3]);
    *(__nv_bfloat162*)(ol + base)     = __halves2bfloat162(l[0], l[1]);
    *(__nv_bfloat162*)(ol + base + 2) = __halves2bfloat162(l[2], l[3]);
}

// ---------------- bf16x3 mma GEMM: verified compute, cp.async 3-stage ring ----------------
#define TILE_B 10240          // one operand tile: 128 rows * 80B
#define STG_B  (4*TILE_B)     // Ah|Al|Bh|Bl per k-stage
#define GEMM_SMEM (3*STG_B)   // 122880

template<int PHASE>
__global__ __launch_bounds__(256, 1)
void gemm_mma(const float* __restrict__ bias, float* __restrict__ out_p)
{
    constexpr int Ntot = (PHASE == 0) ? NQKV : CC;
    const __nv_bfloat16* __restrict__ pAh = (PHASE == 0) ? g_Xh  : g_AOh;
    const __nv_bfloat16* __restrict__ pAl = (PHASE == 0) ? g_Xl  : g_AOl;
    const __nv_bfloat16* __restrict__ pBh = (PHASE == 0) ? g_Wqh : g_Wph;
    const __nv_bfloat16* __restrict__ pBl = (PHASE == 0) ? g_Wql : g_Wpl;
    float* __restrict__ out = (PHASE == 0) ? g_qkv : out_p;

    extern __shared__ char smraw[];
    const uint32_t sb = smem_u32(smraw);
    const int tid  = threadIdx.x;
    const int lane = tid & 31;
    const int wid  = tid >> 5;
    const int wm   = wid & 3;
    const int wn   = wid >> 2;

    const int nT = Ntot / 128;
    int id  = blockIdx.x;
    int gsz = 8 * nT;
    int bm  = (id / gsz) * 8 + (id % gsz) % 8;
    int bn  = (id % gsz) / 8;
    const int m0 = bm * 128, n0 = bn * 128;

    const int r0 = tid >> 2, sg = tid & 3;
    const size_t aoff = (size_t)(m0 + r0)*CC + sg*8;
    const size_t boff = (size_t)(n0 + r0)*CC + sg*8;
    const uint32_t so = (uint32_t)(r0*80 + sg*16);

    auto issue_stage = [&](int s) {
        uint32_t da = sb + (uint32_t)(s % 3)*STG_B + so;
        size_t ks = (size_t)s*32;
        cp16(da,                   pAh + aoff + ks);
        cp16(da + 5120,            pAh + aoff + (size_t)64*CC + ks);
        cp16(da + TILE_B,          pAl + aoff + ks);
        cp16(da + TILE_B + 5120,   pAl + aoff + (size_t)64*CC + ks);
        cp16(da + 2*TILE_B,        pBh + boff + ks);
        cp16(da + 2*TILE_B + 5120, pBh + boff + (size_t)64*CC + ks);
        cp16(da + 3*TILE_B,        pBl + boff + ks);
        cp16(da + 3*TILE_B + 5120, pBl + boff + (size_t)64*CC + ks);
        asm volatile("cp.async.commit_group;");
    };

    float acc[2][8][4];
    #pragma unroll
    for (int mt = 0; mt < 2; mt++)
        #pragma unroll
        for (int nt = 0; nt < 8; nt++)
            #pragma unroll
            for (int q = 0; q < 4; q++) acc[mt][nt][q] = 0.f;

    const int NS = CC / 32;   // 64
    issue_stage(0);
    issue_stage(1);
    for (int s = 0; s < NS; s++) {
        asm volatile("cp.async.wait_group 1;" ::: "memory");
        __syncthreads();
        if (s + 2 < NS) issue_stage(s + 2);

        const char* cAh = smraw + (size_t)(s % 3)*STG_B;
        const char* cAl = cAh + TILE_B;
        const char* cBh = cAh + 2*TILE_B;
        const char* cBl = cAh + 3*TILE_B;

        #pragma unroll
        for (int kc = 0; kc < 2; kc++) {
            uint32_t ah[2][4], al[2][4], bh[8][2], bl[8][2];
            #pragma unroll
            for (int mt = 0; mt < 2; mt++) {
                uint32_t fr = (uint32_t)((wm*32 + mt*16 + (lane>>2))*80 + kc*32 + (lane&3)*4);
                ah[mt][0] = *(const uint32_t*)(cAh + fr);
                ah[mt][1] = *(const uint32_t*)(cAh + fr + 8*80);
                ah[mt][2] = *(const uint32_t*)(cAh + fr + 16);
                ah[mt][3] = *(const uint32_t*)(cAh + fr + 8*80 + 16);
                al[mt][0] = *(const uint32_t*)(cAl + fr);
                al[mt][1] = *(const uint32_t*)(cAl + fr + 8*80);
                al[mt][2] = *(const uint32_t*)(cAl + fr + 16);
                al[mt][3] = *(const uint32_t*)(cAl + fr + 8*80 + 16);
            }
            #pragma unroll
            for (int nt = 0; nt < 8; nt++) {
                uint32_t fb = (uint32_t)((wn*64 + nt*8 + (lane>>2))*80 + kc*32 + (lane&3)*4);
                bh[nt][0] = *(const uint32_t*)(cBh + fb);
                bh[nt][1] = *(const uint32_t*)(cBh + fb + 16);
                bl[nt][0] = *(const uint32_t*)(cBl + fb);
                bl[nt][1] = *(const uint32_t*)(cBl + fb + 16);
            }
            #pragma unroll
            for (int mt = 0; mt < 2; mt++)
                #pragma unroll
                for (int nt = 0; nt < 8; nt++) {
                    mma16816(acc[mt][nt], ah[mt], bh[nt]);
                    mma16816(acc[mt][nt], ah[mt], bl[nt]);
                    mma16816(acc[mt][nt], al[mt], bh[nt]);
                }
        }
    }

    const int gid = lane >> 2, tig = lane & 3;
    #pragma unroll
    for (int mt = 0; mt < 2; mt++) {
        int m = m0 + wm*32 + mt*16 + gid;
        #pragma unroll
        for (int nt = 0; nt < 8; nt++) {
            int n = n0 + wn*64 + nt*8 + tig*2;
            float bv0 = bias[n], bv1 = bias[n+1];
            *(float2*)(out + (size_t)m*Ntot + n)     = make_float2(acc[mt][nt][0] + bv0, acc[mt][nt][1] + bv1);
            *(float2*)(out + (size_t)(m+8)*Ntot + n) = make_float2(acc[mt][nt][2] + bv0, acc[mt][nt][3] + bv1);
        }
    }
}

// ---------------- RoPE + scatter -> bf16 hi/lo Q,K,V ----------------
__global__ void rope_scatter_kernel() {
    size_t i = (size_t)blockIdx.x * blockDim.x + threadIdx.x;
    if (i >= (size_t)MM*NQKV/2) return;
    size_t e = 2*i;
    int m = (int)(e / NQKV);
    int n = (int)(e % NQKV);
    float2 v = *(const float2*)(g_qkv + (size_t)m*NQKV + n);
    int which = n / CC;
    int w2 = n % CC;
    int h = w2 >> 7, d = w2 & 127;
    int bi = m / TT, t = m % TT;
    float o0 = v.x, o1 = v.y;
    if (which != 2) {
        float c = g_cos[t*64 + (d >> 1)], s = g_sin[t*64 + (d >> 1)];
        o0 = v.x*c - v.y*s;
        o1 = v.x*s + v.y*c;
    }
    __nv_bfloat16 h0 = __float2bfloat16(o0), h1 = __float2bfloat16(o1);
    __nv_bfloat16 l0 = __float2bfloat16(o0 - __bfloat162float(h0));
    __nv_bfloat16 l1 = __float2bfloat16(o1 - __bfloat162float(h1));
    __nv_bfloat16* ph = (which == 0) ? g_Qh : (which == 1) ? g_Kh : g_Vh;
    __nv_bfloat16* pl = (which == 0) ? g_Ql : (which == 1) ? g_Kl : g_Vl;
    size_t off = ((size_t)(bi*HH + h)*TT + t)*DD + d;
    *(__nv_bfloat162*)(ph + off) = __halves2bfloat162(h0, h1);
    *(__nv_bfloat162*)(pl + off) = __halves2bfloat162(l0, l1);
}

// ---------------- V transpose: [bh][t][d] -> [bh][d][t] (hi+lo) ----------------
__global__ void transpose_v_kernel() {
    __shared__ __nv_bfloat16 th[64][66], tl[64][66];
    int bh = blockIdx.y;
    int t0 = (blockIdx.x & 31) * 64;
    int d0 = (blockIdx.x >> 5) * 64;
    const __nv_bfloat16* Vh = g_Vh + (size_t)bh*TT*DD;
    const __nv_bfloat16* Vl = g_Vl + (size_t)bh*TT*DD;
    int tid = threadIdx.x;
    #pragma unroll
    for (int p = 0; p < 8; p++) {
        int idx = tid + p*256;
        int r = idx >> 5, c = (idx & 31) * 2;
        *(uint32_t*)&th[r][c] = *(const uint32_t*)(Vh + (size_t)(t0+r)*DD + d0 + c);
        *(uint32_t*)&tl[r][c] = *(const uint32_t*)(Vl + (size_t)(t0+r)*DD + d0 + c);
    }
    __syncthreads();
    __nv_bfloat16* Oth = g_Vth + (size_t)bh*DD*TT;
    __nv_bfloat16* Otl = g_Vtl + (size_t)bh*DD*TT;
    #pragma unroll
    for (int p = 0; p < 8; p++) {
        int idx = tid + p*256;
        int d = idx >> 5, t = (idx & 31) * 2;
        *(uint32_t*)(Oth + (size_t)(d0+d)*TT + t0 + t) = pack2(th[t][d], th[t+1][d]);
        *(uint32_t*)(Otl + (size_t)(d0+d)*TT + t0 + t) = pack2(tl[t][d], tl[t+1][d]);
    }
}

// ---------------- mma.sync flash attention: cp.async double-buffered K/V ----------------
#define AQ_STR 272        // Q/K smem row stride
#define AV_STR 144        // Vt smem row stride
#define SM_QH 0
#define SM_QL 34816
#define A_KBUF 34816      // per K buffer: KH 17408 + KL 17408
#define A_VBUF 36864      // per V buffer: VH 18432 + VL 18432
#define SM_K0 69632
#define SM_V0 (SM_K0 + 2*A_KBUF)          // 139264
#define ATTN_SMEM (SM_V0 + 2*A_VBUF)      // 212992

__global__ __launch_bounds__(256, 1) void attn_mma_kernel() {
    extern __shared__ char smc[];
    const uint32_t sb = smem_u32(smc);
    const int tid  = threadIdx.x;
    const int lane = tid & 31;
    const int w    = tid >> 5;
    const int r1   = lane >> 2;
    const int c4   = lane & 3;
    const int bh   = blockIdx.y;
    const int q0   = (int)(gridDim.x - 1 - blockIdx.x) * 128;

    const __nv_bfloat16* Qh = g_Qh + (size_t)bh*TT*DD;
    const __nv_bfloat16* Ql = g_Ql + (size_t)bh*TT*DD;
    const __nv_bfloat16* Kh = g_Kh + (size_t)bh*TT*DD;
    const __nv_bfloat16* Kl = g_Kl + (size_t)bh*TT*DD;
    const __nv_bfloat16* Vth = g_Vth + (size_t)bh*DD*TT;
    const __nv_bfloat16* Vtl = g_Vtl + (size_t)bh*DD*TT;

    auto issue_kv = [&](int kt, int b) {
        uint32_t kb = sb + SM_K0 + (uint32_t)b*A_KBUF;
        uint32_t vb = sb + SM_V0 + (uint32_t)b*A_VBUF;
        #pragma unroll
        for (int p = 0; p < 4; p++) {               // K: 64 rows x 256B, 16 chunks/row
            int c = tid + p*256;
            int row = c >> 4, c16 = c & 15;
            cp16(kb +         row*AQ_STR + c16*16, Kh + (size_t)(kt*64+row)*DD + c16*8);
            cp16(kb + 17408 + row*AQ_STR + c16*16, Kl + (size_t)(kt*64+row)*DD + c16*8);
        }
        #pragma unroll
        for (int p = 0; p < 4; p++) {               // Vt: 128 rows x 128B, 8 chunks/row
            int c = tid + p*256;
            int row = c >> 3, c8 = c & 7;
            cp16(vb +         row*AV_STR + c8*16, Vth + (size_t)row*TT + kt*64 + c8*8);
            cp16(vb + 18432 + row*AV_STR + c8*16, Vtl + (size_t)row*TT + kt*64 + c8*8);
        }
        asm volatile("cp.async.commit_group;");
    };

    issue_kv(0, 0);

    // Q tile 128x128, hi+lo
    #pragma unroll
    for (int p = 0; p < 8; p++) {
        int idx = tid + p*256;
        int row = idx >> 4, c16 = idx & 15;
        *(float4*)(smc + SM_QH + row*AQ_STR + c16*16) = *(const float4*)(Qh + (size_t)(q0+row)*DD + c16*8);
        *(float4*)(smc + SM_QL + row*AQ_STR + c16*16) = *(const float4*)(Ql + (size_t)(q0+row)*DD + c16*8);
    }

    const int qrow1 = q0 + w*16 + r1;
    const int qrow2 = qrow1 + 8;
    float m1 = -1e30f, m2 = -1e30f, l1 = 0.f, l2 = 0.f;
    float O[16][4];
    #pragma unroll
    for (int vt = 0; vt < 16; vt++)
        #pragma unroll
        for (int q = 0; q < 4; q++) O[vt][q] = 0.f;

    const float scale = 0.08838834764831845f;
    const int ktmax = q0/64 + 1;

    for (int kt = 0; kt <= ktmax; kt++) {
        asm volatile("cp.async.wait_group 0;" ::: "memory");
        __syncthreads();                       // buf[kt&1] ready; all warps done with buf[(kt+1)&1]
        if (kt + 1 <= ktmax) issue_kv(kt + 1, (kt + 1) & 1);

        const char* cKH = smc + SM_K0 + (size_t)(kt & 1)*A_KBUF;
        const char* cKL = cKH + 17408;
        const char* cVH = smc + SM_V0 + (size_t)(kt & 1)*A_VBUF;
        const char* cVL = cVH + 18432;

        // S = Q K^T  (bf16x3)
        float S[8][4];
        #pragma unroll
        for (int nt = 0; nt < 8; nt++)
            #pragma unroll
            for (int q = 0; q < 4; q++) S[nt][q] = 0.f;
        #pragma unroll
        for (int kc = 0; kc < 8; kc++) {
            uint32_t ah[4], al[4];
            uint32_t fr = (uint32_t)((w*16 + r1)*AQ_STR + kc*32 + c4*4);
            ah[0] = *(const uint32_t*)(smc + SM_QH + fr);
            ah[1] = *(const uint32_t*)(smc + SM_QH + fr + 8*AQ_STR);
            ah[2] = *(const uint32_t*)(smc + SM_QH + fr + 16);
            ah[3] = *(const uint32_t*)(smc + SM_QH + fr + 8*AQ_STR + 16);
            al[0] = *(const uint32_t*)(smc + SM_QL + fr);
            al[1] = *(const uint32_t*)(smc + SM_QL + fr + 8*AQ_STR);
            al[2] = *(const uint32_t*)(smc + SM_QL + fr + 16);
            al[3] = *(const uint32_t*)(smc + SM_QL + fr + 8*AQ_STR + 16);
            #pragma unroll
            for (int nt = 0; nt < 8; nt++) {
                uint32_t fb = (uint32_t)((nt*8 + r1)*AQ_STR + kc*32 + c4*4);
                uint32_t bh[2], bl[2];
                bh[0] = *(const uint32_t*)(cKH + fb);
                bh[1] = *(const uint32_t*)(cKH + fb + 16);
                bl[0] = *(const uint32_t*)(cKL + fb);
                bl[1] = *(const uint32_t*)(cKL + fb + 16);
                mma16816(S[nt], ah, bh);
                mma16816(S[nt], ah, bl);
                mma16816(S[nt], al, bh);
            }
        }

        // scale + causal mask + row max
        float mx1 = -1e30f, mx2 = -1e30f;
        #pragma unroll
        for (int nt = 0; nt < 8; nt++) {
            int col0 = kt*64 + nt*8 + 2*c4;
            S[nt][0] = (col0     <= qrow1) ? S[nt][0]*scale : -1e30f;
            S[nt][1] = (col0 + 1 <= qrow1) ? S[nt][1]*scale : -1e30f;
            S[nt][2] = (col0     <= qrow2) ? S[nt][2]*scale : -1e30f;
            S[nt][3] = (col0 + 1 <= qrow2) ? S[nt][3]*scale : -1e30f;
            mx1 = fmaxf(mx1, fmaxf(S[nt][0], S[nt][1]));
            mx2 = fmaxf(mx2, fmaxf(S[nt][2], S[nt][3]));
        }
        #pragma unroll
        for (int off = 1; off <= 2; off <<= 1) {
            mx1 = fmaxf(mx1, __shfl_xor_sync(0xffffffffu, mx1, off));
            mx2 = fmaxf(mx2, __shfl_xor_sync(0xffffffffu, mx2, off));
        }
        float mn1 = fmaxf(m1, mx1), mn2 = fmaxf(m2, mx2);
        float al1 = __expf(m1 - mn1), al2 = __expf(m2 - mn2);
        m1 = mn1; m2 = mn2;

        // P = exp(S - m), hi/lo split, row sums
        uint32_t ph1[8], ph2[8], pl1[8], pl2[8];
        float rs1 = 0.f, rs2 = 0.f;
        #pragma unroll
        for (int nt = 0; nt < 8; nt++) {
            float p00 = __expf(S[nt][0] - mn1), p01 = __expf(S[nt][1] - mn1);
            float p10 = __expf(S[nt][2] - mn2), p11 = __expf(S[nt][3] - mn2);
            rs1 += p00 + p01; rs2 += p10 + p11;
            __nv_bfloat16 h00 = __float2bfloat16(p00), h01 = __float2bfloat16(p01);
            __nv_bfloat16 h10 = __float2bfloat16(p10), h11 = __float2bfloat16(p11);
            ph1[nt] = pack2(h00, h01);
            ph2[nt] = pack2(h10, h11);
            pl1[nt] = pack2(__float2bfloat16(p00 - __bfloat162float(h00)),
                            __float2bfloat16(p01 - __bfloat162float(h01)));
            pl2[nt] = pack2(__float2bfloat16(p10 - __bfloat162float(h10)),
                            __float2bfloat16(p11 - __bfloat162float(h11)));
        }
        #pragma unroll
        for (int off = 1; off <= 2; off <<= 1) {
            rs1 += __shfl_xor_sync(0xffffffffu, rs1, off);
            rs2 += __shfl_xor_sync(0xffffffffu, rs2, off);
        }
        l1 = l1*al1 + rs1;
        l2 = l2*al2 + rs2;
        #pragma unroll
        for (int vt = 0; vt < 16; vt++) {
            O[vt][0] *= al1; O[vt][1] *= al1;
            O[vt][2] *= al2; O[vt][3] *= al2;
        }

        // O += P V  (bf16x3; P fragments direct from registers)
        #pragma unroll
        for (int kc = 0; kc < 4; kc++) {
            uint32_t pa[4] = { ph1[2*kc], ph2[2*kc], ph1[2*kc+1], ph2[2*kc+1] };
            uint32_t pb[4] = { pl1[2*kc], pl2[2*kc], pl1[2*kc+1], pl2[2*kc+1] };
            #pragma unroll
            for (int vt = 0; vt < 16; vt++) {
                uint32_t fb = (uint32_t)((vt*8 + r1)*AV_STR + kc*32 + c4*4);
                uint32_t bh[2], bl[2];
                bh[0] = *(const uint32_t*)(cVH + fb);
                bh[1] = *(const uint32_t*)(cVH + fb + 16);
                bl[0] = *(const uint32_t*)(cVL + fb);
                bl[1] = *(const uint32_t*)(cVL + fb + 16);
                mma16816(O[vt], pa, bh);
                mma16816(O[vt], pa, bl);
                mma16816(O[vt], pb, bh);
            }
        }
    }

    // epilogue: normalize, split hi/lo, write g_AOh/g_AOl
    const int b = bh >> 4, h = bh & 15;
    const float i1 = 1.0f / l1, i2 = 1.0f / l2;
    const size_t mrow1 = (size_t)(b*TT + qrow1) * CC;
    const size_t mrow2 = (size_t)(b*TT + qrow2) * CC;
    #pragma unroll
    for (int vt = 0; vt < 16; vt++) {
        int col = h*DD + vt*8 + 2*c4;
        float o00 = O[vt][0]*i1, o01 = O[vt][1]*i1;
        float o10 = O[vt][2]*i2, o11 = O[vt][3]*i2;
        __nv_bfloat16 h00 = __float2bfloat16(o00), h01 = __float2bfloat16(o01);
        __nv_bfloat16 h10 = __float2bfloat16(o10), h11 = __float2bfloat16(o11);
        *(__nv_bfloat162*)(g_AOh + mrow1 + col) = __halves2bfloat162(h00, h01);
        *(__nv_bfloat162*)(g_AOh + mrow2 + col) = __halves2bfloat162(h10, h11);
        *(__nv_bfloat162*)(g_AOl + mrow1 + col) = __halves2bfloat162(
            __float2bfloat16(o00 - __bfloat162float(h00)), __float2bfloat16(o01 - __bfloat162float(h01)));
        *(__nv_bfloat162*)(g_AOl + mrow2 + col) = __halves2bfloat162(
            __float2bfloat16(o10 - __bfloat162float(h10)), __float2bfloat16(o11 - __bfloat162float(h11)));
    }
}

// ---------------- launcher (no __device__ symbols as host-side args) ----------------
extern "C" void kernel_launch(void* const* d_in, const int* in_sizes, int n_in,
                              void* d_out, int out_size) {
    const float* x      = (const float*)d_in[0];
    const float* W_attn = (const float*)d_in[1];
    const float* b_attn = (const float*)d_in[2];
    const float* W_proj = (const float*)d_in[3];
    const float* b_proj = (const float*)d_in[4];
    float* out = (float*)d_out;

    cudaFuncSetAttribute(gemm_mma<0>, cudaFuncAttributeMaxDynamicSharedMemorySize, GEMM_SMEM);
    cudaFuncSetAttribute(gemm_mma<1>, cudaFuncAttributeMaxDynamicSharedMemorySize, GEMM_SMEM);
    cudaFuncSetAttribute(attn_mma_kernel, cudaFuncAttributeMaxDynamicSharedMemorySize, ATTN_SMEM);

    rope_init_kernel<<<(TT*(DD/2) + 255)/256, 256>>>();
    conv_split_kernel<<<(MM*CC/2 + 255)/256, 256>>>(x);
    conv_wT_kernel<0><<<dim3(NQKV/32, CC/32), 256>>>(W_attn);
    conv_wT_kernel<1><<<dim3(CC/32,   CC/32), 256>>>(W_proj);

    gemm_mma<0><<<(MM/128)*(NQKV/128), 256, GEMM_SMEM>>>(b_attn, nullptr);

    rope_scatter_kernel<<<(int)(((size_t)MM*NQKV/2 + 255)/256), 256>>>();

    transpose_v_kernel<<<dim3(64, BB*HH), 256>>>();

    attn_mma_kernel<<<dim3(TT/128, BB*HH), 256, ATTN_SMEM>>>();

    gemm_mma<1><<<(MM/128)*(CC/128), 256, GEMM_SMEM>>>(b_proj, out);
}

// round 15
// speedup vs baseline: 2.2110x; 1.0554x over previous
#include <cuda_runtime.h>
#include <cuda_bf16.h>
#include <math.h>
#include <cstdint>

#define BB 2
#define TT 2048
#define CC 2048
#define HH 16
#define DD 128
#define MM (BB*TT)        // 4096
#define NQKV (3*CC)       // 6144

// ---------------- scratch (__device__ globals; NEVER passed as host-side kernel args) ----------------
static __device__ __align__(256) float g_cos[TT*(DD/2)];
static __device__ __align__(256) float g_sin[TT*(DD/2)];
static __device__ __align__(256) __nv_bfloat16 g_Xh [(size_t)MM*CC],   g_Xl [(size_t)MM*CC];
static __device__ __align__(256) __nv_bfloat16 g_Wqh[(size_t)NQKV*CC], g_Wql[(size_t)NQKV*CC];
static __device__ __align__(256) __nv_bfloat16 g_Wph[(size_t)CC*CC],   g_Wpl[(size_t)CC*CC];
static __device__ __align__(256) __nv_bfloat16 g_AOh[(size_t)MM*CC],   g_AOl[(size_t)MM*CC];
static __device__ __align__(256) __nv_bfloat16 g_Qh[(size_t)BB*HH*TT*DD], g_Ql[(size_t)BB*HH*TT*DD];
static __device__ __align__(256) __nv_bfloat16 g_Kh[(size_t)BB*HH*TT*DD], g_Kl[(size_t)BB*HH*TT*DD];
static __device__ __align__(256) __nv_bfloat16 g_Vh[(size_t)BB*HH*TT*DD], g_Vl[(size_t)BB*HH*TT*DD];
static __device__ __align__(256) __nv_bfloat16 g_Vth[(size_t)BB*HH*TT*DD], g_Vtl[(size_t)BB*HH*TT*DD];

__device__ __forceinline__ void mma16816(float* c, const uint32_t* a, const uint32_t* b){
    asm volatile("mma.sync.aligned.m16n8k16.row.col.f32.bf16.bf16.f32 "
                 "{%0,%1,%2,%3}, {%4,%5,%6,%7}, {%8,%9}, {%0,%1,%2,%3};"
                 : "+f"(c[0]), "+f"(c[1]), "+f"(c[2]), "+f"(c[3])
                 : "r"(a[0]), "r"(a[1]), "r"(a[2]), "r"(a[3]), "r"(b[0]), "r"(b[1]));
}
__device__ __forceinline__ void ldx4(uint32_t* r, uint32_t addr){
    asm volatile("ldmatrix.sync.aligned.m8n8.x4.shared.b16 {%0,%1,%2,%3}, [%4];"
                 : "=r"(r[0]), "=r"(r[1]), "=r"(r[2]), "=r"(r[3]) : "r"(addr));
}
__device__ __forceinline__ uint32_t pack2(__nv_bfloat16 a, __nv_bfloat16 b){
    return ((uint32_t)*(uint16_t*)&b << 16) | *(uint16_t*)&a;
}
__device__ __forceinline__ uint32_t smem_u32(const void* p){
    uint32_t a;
    asm("{ .reg .u64 t; cvta.to.shared.u64 t, %1; cvt.u32.u64 %0, t; }" : "=r"(a) : "l"(p));
    return a;
}
__device__ __forceinline__ void cp16(uint32_t dst, const void* src){
    asm volatile("cp.async.cg.shared.global [%0], [%1], 16;" :: "r"(dst), "l"(src));
}

// ---------------- init ----------------
__global__ void rope_init_kernel() {
    int idx = blockIdx.x * blockDim.x + threadIdx.x;
    if (idx >= TT*(DD/2)) return;
    int t = idx / (DD/2);
    int i = idx - t*(DD/2);
    float inv = powf(10000.0f, -(float)(2*i) / (float)DD);
    float ang = (float)t * inv;
    g_cos[idx] = cosf(ang);
    g_sin[idx] = sinf(ang);
}

// ---------------- conversions ----------------
__global__ void conv_split_kernel(const float* __restrict__ xin) {
    int i = blockIdx.x * blockDim.x + threadIdx.x;
    if (i >= MM*CC/2) return;
    float2 v = ((const float2*)xin)[i];
    __nv_bfloat16 h0 = __float2bfloat16(v.x), h1 = __float2bfloat16(v.y);
    __nv_bfloat16 l0 = __float2bfloat16(v.x - __bfloat162float(h0));
    __nv_bfloat16 l1 = __float2bfloat16(v.y - __bfloat162float(h1));
    ((__nv_bfloat162*)g_Xh)[i] = __halves2bfloat162(h0, h1);
    ((__nv_bfloat162*)g_Xl)[i] = __halves2bfloat162(l0, l1);
}

template<int SEL>
__global__ void conv_wT_kernel(const float* __restrict__ W) {
    constexpr int N = (SEL == 0) ? NQKV : CC;
    __nv_bfloat16* oh = (SEL == 0) ? g_Wqh : g_Wph;
    __nv_bfloat16* ol = (SEL == 0) ? g_Wql : g_Wpl;
    __shared__ float t[32][33];
    int k0 = blockIdx.y * 32, n0 = blockIdx.x * 32;
    int tid = threadIdx.x;
    #pragma unroll
    for (int r = 0; r < 4; r++) {
        int kk = (tid >> 5) + r*8, nn = tid & 31;
        t[kk][nn] = W[(size_t)(k0+kk)*N + n0 + nn];
    }
    __syncthreads();
    int nn = tid >> 3, ks = (tid & 7) * 4;
    size_t base = (size_t)(n0+nn)*CC + k0 + ks;
    float v[4];
    #pragma unroll
    for (int j = 0; j < 4; j++) v[j] = t[ks+j][nn];
    __nv_bfloat16 h[4], l[4];
    #pragma unroll
    for (int j = 0; j < 4; j++) {
        h[j] = __float2bfloat16(v[j]);
        l[j] = __float2bfloat16(v[j] - __bfloat162float(h[j]));
    }
    *(__nv_bfloat162*)(oh + base)     = __halves2bfloat162(h[0], h[1]);
    *(__nv_bfloat162*)(oh + base + 2) = __halves2bfloat162(h[2], h[3]);
    *(__nv_bfloat162*)(ol + base)     = __halves2bfloat162(l[0], l[1]);
    *(__nv_bfloat162*)(ol + base + 2) = __halves2bfloat162(l[2], l[3]);
}

// ---------------- bf16x3 mma GEMM: cp.async ring + ldmatrix; PHASE0 fuses RoPE+scatter ----------------
#define TILE_B 10240          // one operand tile: 128 rows * 80B
#define STG_B  (4*TILE_B)     // Ah|Al|Bh|Bl per k-stage
#define GEMM_SMEM (3*STG_B)   // 122880

template<int PHASE>
__global__ __launch_bounds__(256, 1)
void gemm_mma(const float* __restrict__ bias, float* __restrict__ out_p)
{
    constexpr int Ntot = (PHASE == 0) ? NQKV : CC;
    const __nv_bfloat16* __restrict__ pAh = (PHASE == 0) ? g_Xh  : g_AOh;
    const __nv_bfloat16* __restrict__ pAl = (PHASE == 0) ? g_Xl  : g_AOl;
    const __nv_bfloat16* __restrict__ pBh = (PHASE == 0) ? g_Wqh : g_Wph;
    const __nv_bfloat16* __restrict__ pBl = (PHASE == 0) ? g_Wql : g_Wpl;

    extern __shared__ char smraw[];
    const uint32_t sb = smem_u32(smraw);
    const int tid  = threadIdx.x;
    const int lane = tid & 31;
    const int wid  = tid >> 5;
    const int wm   = wid & 3;
    const int wn   = wid >> 2;

    const int nT = Ntot / 128;
    int id  = blockIdx.x;
    int gsz = 8 * nT;
    int bm  = (id / gsz) * 8 + (id % gsz) % 8;
    int bn  = (id % gsz) / 8;
    const int m0 = bm * 128, n0 = bn * 128;

    const int r0 = tid >> 2, sg = tid & 3;
    const size_t aoff = (size_t)(m0 + r0)*CC + sg*8;
    const size_t boff = (size_t)(n0 + r0)*CC + sg*8;
    const uint32_t so = (uint32_t)(r0*80 + sg*16);

    auto issue_stage = [&](int s) {
        uint32_t da = sb + (uint32_t)(s % 3)*STG_B + so;
        size_t ks = (size_t)s*32;
        cp16(da,                   pAh + aoff + ks);
        cp16(da + 5120,            pAh + aoff + (size_t)64*CC + ks);
        cp16(da + TILE_B,          pAl + aoff + ks);
        cp16(da + TILE_B + 5120,   pAl + aoff + (size_t)64*CC + ks);
        cp16(da + 2*TILE_B,        pBh + boff + ks);
        cp16(da + 2*TILE_B + 5120, pBh + boff + (size_t)64*CC + ks);
        cp16(da + 3*TILE_B,        pBl + boff + ks);
        cp16(da + 3*TILE_B + 5120, pBl + boff + (size_t)64*CC + ks);
        asm volatile("cp.async.commit_group;");
    };

    float acc[2][8][4];
    #pragma unroll
    for (int mt = 0; mt < 2; mt++)
        #pragma unroll
        for (int nt = 0; nt < 8; nt++)
            #pragma unroll
            for (int q = 0; q < 4; q++) acc[mt][nt][q] = 0.f;

    // ldmatrix per-lane offsets within a stage buffer
    const uint32_t aOff = (uint32_t)((wm*32 + (lane & 15))*80 + (lane >> 4)*16);
    const uint32_t bOff = (uint32_t)((wn*64 + (lane >> 4)*8 + (lane & 7))*80 + ((lane >> 3) & 1)*16);

    const int NS = CC / 32;   // 64
    issue_stage(0);
    issue_stage(1);
    for (int s = 0; s < NS; s++) {
        asm volatile("cp.async.wait_group 1;" ::: "memory");
        __syncthreads();
        if (s + 2 < NS) issue_stage(s + 2);

        const uint32_t sA = sb + (uint32_t)(s % 3)*STG_B;
        const uint32_t sB = sA + 2*TILE_B;

        #pragma unroll
        for (int kc = 0; kc < 2; kc++) {
            uint32_t ah[2][4], al[2][4], bh[8][2], bl[8][2];
            #pragma unroll
            for (int mt = 0; mt < 2; mt++) {
                uint32_t aa = sA + aOff + mt*16*80 + kc*32;
                ldx4(ah[mt], aa);
                ldx4(al[mt], aa + TILE_B);
            }
            #pragma unroll
            for (int np = 0; np < 4; np++) {
                uint32_t ba = sB + bOff + np*16*80 + kc*32;
                uint32_t r[4];
                ldx4(r, ba);
                bh[2*np][0]   = r[0]; bh[2*np][1]   = r[1];
                bh[2*np+1][0] = r[2]; bh[2*np+1][1] = r[3];
                ldx4(r, ba + TILE_B);
                bl[2*np][0]   = r[0]; bl[2*np][1]   = r[1];
                bl[2*np+1][0] = r[2]; bl[2*np+1][1] = r[3];
            }
            #pragma unroll
            for (int mt = 0; mt < 2; mt++)
                #pragma unroll
                for (int nt = 0; nt < 8; nt++) {
                    mma16816(acc[mt][nt], ah[mt], bh[nt]);
                    mma16816(acc[mt][nt], ah[mt], bl[nt]);
                    mma16816(acc[mt][nt], al[mt], bh[nt]);
                }
        }
    }

    const int gid = lane >> 2, tig = lane & 3;
    if (PHASE == 1) {
        float* __restrict__ out = out_p;
        #pragma unroll
        for (int mt = 0; mt < 2; mt++) {
            int m = m0 + wm*32 + mt*16 + gid;
            #pragma unroll
            for (int nt = 0; nt < 8; nt++) {
                int n = n0 + wn*64 + nt*8 + tig*2;
                float bv0 = bias[n], bv1 = bias[n+1];
                *(float2*)(out + (size_t)m*Ntot + n)     = make_float2(acc[mt][nt][0] + bv0, acc[mt][nt][1] + bv1);
                *(float2*)(out + (size_t)(m+8)*Ntot + n) = make_float2(acc[mt][nt][2] + bv0, acc[mt][nt][3] + bv1);
            }
        }
    } else {
        // fused bias + RoPE + scatter to bf16 hi/lo Q/K/V (math identical to verified rope_scatter)
        #pragma unroll
        for (int mt = 0; mt < 2; mt++) {
            int m = m0 + wm*32 + mt*16 + gid;
            int bi = m >> 11;              // m / TT
            int t0 = m & 2047, t1 = t0 + 8;
            #pragma unroll
            for (int nt = 0; nt < 8; nt++) {
                int n = n0 + wn*64 + nt*8 + tig*2;     // even
                float bv0 = bias[n], bv1 = bias[n+1];
                float c0 = acc[mt][nt][0] + bv0, c1 = acc[mt][nt][1] + bv1;
                float c2 = acc[mt][nt][2] + bv0, c3 = acc[mt][nt][3] + bv1;
                int which = n / CC;
                int w2 = n - which*CC;
                int h = w2 >> 7, d = w2 & 127;          // d even
                if (which != 2) {
                    float cs0 = g_cos[t0*64 + (d >> 1)], sn0 = g_sin[t0*64 + (d >> 1)];
                    float cs1 = g_cos[t1*64 + (d >> 1)], sn1 = g_sin[t1*64 + (d >> 1)];
                    float a0 = c0, a1 = c1; c0 = a0*cs0 - a1*sn0; c1 = a0*sn0 + a1*cs0;
                    float a2 = c2, a3 = c3; c2 = a2*cs1 - a3*sn1; c3 = a2*sn1 + a3*cs1;
                }
                __nv_bfloat16* ph = (which == 0) ? g_Qh : (which == 1) ? g_Kh : g_Vh;
                __nv_bfloat16* pl = (which == 0) ? g_Ql : (which == 1) ? g_Kl : g_Vl;
                size_t off0 = ((size_t)(bi*HH + h)*TT + t0)*DD + d;
                size_t off1 = off0 + (size_t)8*DD;
                __nv_bfloat16 h0 = __float2bfloat16(c0), h1 = __float2bfloat16(c1);
                __nv_bfloat16 h2 = __float2bfloat16(c2), h3 = __float2bfloat16(c3);
                *(__nv_bfloat162*)(ph + off0) = __halves2bfloat162(h0, h1);
                *(__nv_bfloat162*)(ph + off1) = __halves2bfloat162(h2, h3);
                *(__nv_bfloat162*)(pl + off0) = __halves2bfloat162(
                    __float2bfloat16(c0 - __bfloat162float(h0)), __float2bfloat16(c1 - __bfloat162float(h1)));
                *(__nv_bfloat162*)(pl + off1) = __halves2bfloat162(
                    __float2bfloat16(c2 - __bfloat162float(h2)), __float2bfloat16(c3 - __bfloat162float(h3)));
            }
        }
    }
}

// ---------------- V transpose: [bh][t][d] -> [bh][d][t] (hi+lo) ----------------
__global__ void transpose_v_kernel() {
    __shared__ __nv_bfloat16 th[64][66], tl[64][66];
    int bh = blockIdx.y;
    int t0 = (blockIdx.x & 31) * 64;
    int d0 = (blockIdx.x >> 5) * 64;
    const __nv_bfloat16* Vh = g_Vh + (size_t)bh*TT*DD;
    const __nv_bfloat16* Vl = g_Vl + (size_t)bh*TT*DD;
    int tid = threadIdx.x;
    #pragma unroll
    for (int p = 0; p < 8; p++) {
        int idx = tid + p*256;
        int r = idx >> 5, c = (idx & 31) * 2;
        *(uint32_t*)&th[r][c] = *(const uint32_t*)(Vh + (size_t)(t0+r)*DD + d0 + c);
        *(uint32_t*)&tl[r][c] = *(const uint32_t*)(Vl + (size_t)(t0+r)*DD + d0 + c);
    }
    __syncthreads();
    __nv_bfloat16* Oth = g_Vth + (size_t)bh*DD*TT;
    __nv_bfloat16* Otl = g_Vtl + (size_t)bh*DD*TT;
    #pragma unroll
    for (int p = 0; p < 8; p++) {
        int idx = tid + p*256;
        int d = idx >> 5, t = (idx & 31) * 2;
        *(uint32_t*)(Oth + (size_t)(d0+d)*TT + t0 + t) = pack2(th[t][d], th[t+1][d]);
        *(uint32_t*)(Otl + (size_t)(d0+d)*TT + t0 + t) = pack2(tl[t][d], tl[t+1][d]);
    }
}

// ---------------- mma.sync flash attention: cp.async K/V + ldmatrix fragments ----------------
#define AQ_STR 272
#define AV_STR 144
#define SM_QH 0
#define SM_QL 34816
#define A_KBUF 34816
#define A_VBUF 36864
#define SM_K0 69632
#define SM_V0 (SM_K0 + 2*A_KBUF)          // 139264
#define ATTN_SMEM (SM_V0 + 2*A_VBUF)      // 212992

__global__ __launch_bounds__(256, 1) void attn_mma_kernel() {
    extern __shared__ char smc[];
    const uint32_t sb = smem_u32(smc);
    const int tid  = threadIdx.x;
    const int lane = tid & 31;
    const int w    = tid >> 5;
    const int r1   = lane >> 2;
    const int c4   = lane & 3;
    const int bh   = blockIdx.y;
    const int q0   = (int)(gridDim.x - 1 - blockIdx.x) * 128;

    const __nv_bfloat16* Qh = g_Qh + (size_t)bh*TT*DD;
    const __nv_bfloat16* Ql = g_Ql + (size_t)bh*TT*DD;
    const __nv_bfloat16* Kh = g_Kh + (size_t)bh*TT*DD;
    const __nv_bfloat16* Kl = g_Kl + (size_t)bh*TT*DD;
    const __nv_bfloat16* Vth = g_Vth + (size_t)bh*DD*TT;
    const __nv_bfloat16* Vtl = g_Vtl + (size_t)bh*DD*TT;

    auto issue_kv = [&](int kt, int b) {
        uint32_t kb = sb + SM_K0 + (uint32_t)b*A_KBUF;
        uint32_t vb = sb + SM_V0 + (uint32_t)b*A_VBUF;
        #pragma unroll
        for (int p = 0; p < 4; p++) {
            int c = tid + p*256;
            int row = c >> 4, c16 = c & 15;
            cp16(kb +         row*AQ_STR + c16*16, Kh + (size_t)(kt*64+row)*DD + c16*8);
            cp16(kb + 17408 + row*AQ_STR + c16*16, Kl + (size_t)(kt*64+row)*DD + c16*8);
        }
        #pragma unroll
        for (int p = 0; p < 4; p++) {
            int c = tid + p*256;
            int row = c >> 3, c8 = c & 7;
            cp16(vb +         row*AV_STR + c8*16, Vth + (size_t)row*TT + kt*64 + c8*8);
            cp16(vb + 18432 + row*AV_STR + c8*16, Vtl + (size_t)row*TT + kt*64 + c8*8);
        }
        asm volatile("cp.async.commit_group;");
    };

    issue_kv(0, 0);

    #pragma unroll
    for (int p = 0; p < 8; p++) {
        int idx = tid + p*256;
        int row = idx >> 4, c16 = idx & 15;
        *(float4*)(smc + SM_QH + row*AQ_STR + c16*16) = *(const float4*)(Qh + (size_t)(q0+row)*DD + c16*8);
        *(float4*)(smc + SM_QL + row*AQ_STR + c16*16) = *(const float4*)(Ql + (size_t)(q0+row)*DD + c16*8);
    }

    const int qrow1 = q0 + w*16 + r1;
    const int qrow2 = qrow1 + 8;
    float m1 = -1e30f, m2 = -1e30f, l1 = 0.f, l2 = 0.f;
    float O[16][4];
    #pragma unroll
    for (int vt = 0; vt < 16; vt++)
        #pragma unroll
        for (int q = 0; q < 4; q++) O[vt][q] = 0.f;

    const float scale = 0.08838834764831845f;
    const int ktmax = q0/64 + 1;

    // ldmatrix per-lane offsets
    const uint32_t aOffQ = (uint32_t)((w*16 + (lane & 15))*AQ_STR + (lane >> 4)*16);
    const uint32_t bOffK = (uint32_t)(((lane >> 4)*8 + (lane & 7))*AQ_STR + ((lane >> 3) & 1)*16);
    const uint32_t bOffV = (uint32_t)(((lane >> 4)*8 + (lane & 7))*AV_STR + ((lane >> 3) & 1)*16);

    for (int kt = 0; kt <= ktmax; kt++) {
        asm volatile("cp.async.wait_group 0;" ::: "memory");
        __syncthreads();
        if (kt + 1 <= ktmax) issue_kv(kt + 1, (kt + 1) & 1);

        const uint32_t kbH = sb + SM_K0 + (uint32_t)(kt & 1)*A_KBUF;
        const uint32_t vbH = sb + SM_V0 + (uint32_t)(kt & 1)*A_VBUF;

        // S = Q K^T  (bf16x3)
        float S[8][4];
        #pragma unroll
        for (int nt = 0; nt < 8; nt++)
            #pragma unroll
            for (int q = 0; q < 4; q++) S[nt][q] = 0.f;
        #pragma unroll
        for (int kc = 0; kc < 8; kc++) {
            uint32_t ah[4], al[4];
            uint32_t aa = sb + SM_QH + aOffQ + kc*32;
            ldx4(ah, aa);
            ldx4(al, aa + (SM_QL - SM_QH));
            #pragma unroll
            for (int np = 0; np < 4; np++) {
                uint32_t ka = kbH + bOffK + np*16*AQ_STR + kc*32;
                uint32_t rh[4], rl[4];
                ldx4(rh, ka);
                ldx4(rl, ka + 17408);
                uint32_t bh0[2] = { rh[0], rh[1] }, bh1[2] = { rh[2], rh[3] };
                uint32_t bl0[2] = { rl[0], rl[1] }, bl1[2] = { rl[2], rl[3] };
                mma16816(S[2*np],   ah, bh0);
                mma16816(S[2*np],   ah, bl0);
                mma16816(S[2*np],   al, bh0);
                mma16816(S[2*np+1], ah, bh1);
                mma16816(S[2*np+1], ah, bl1);
                mma16816(S[2*np+1], al, bh1);
            }
        }

        // scale + causal mask + row max
        float mx1 = -1e30f, mx2 = -1e30f;
        #pragma unroll
        for (int nt = 0; nt < 8; nt++) {
            int col0 = kt*64 + nt*8 + 2*c4;
            S[nt][0] = (col0     <= qrow1) ? S[nt][0]*scale : -1e30f;
            S[nt][1] = (col0 + 1 <= qrow1) ? S[nt][1]*scale : -1e30f;
            S[nt][2] = (col0     <= qrow2) ? S[nt][2]*scale : -1e30f;
            S[nt][3] = (col0 + 1 <= qrow2) ? S[nt][3]*scale : -1e30f;
            mx1 = fmaxf(mx1, fmaxf(S[nt][0], S[nt][1]));
            mx2 = fmaxf(mx2, fmaxf(S[nt][2], S[nt][3]));
        }
        #pragma unroll
        for (int off = 1; off <= 2; off <<= 1) {
            mx1 = fmaxf(mx1, __shfl_xor_sync(0xffffffffu, mx1, off));
            mx2 = fmaxf(mx2, __shfl_xor_sync(0xffffffffu, mx2, off));
        }
        float mn1 = fmaxf(m1, mx1), mn2 = fmaxf(m2, mx2);
        float al1 = __expf(m1 - mn1), al2 = __expf(m2 - mn2);
        m1 = mn1; m2 = mn2;

        // P = exp(S - m), hi/lo split, row sums
        uint32_t ph1[8], ph2[8], pl1[8], pl2[8];
        float rs1 = 0.f, rs2 = 0.f;
        #pragma unroll
        for (int nt = 0; nt < 8; nt++) {
            float p00 = __expf(S[nt][0] - mn1), p01 = __expf(S[nt][1] - mn1);
            float p10 = __expf(S[nt][2] - mn2), p11 = __expf(S[nt][3] - mn2);
            rs1 += p00 + p01; rs2 += p10 + p11;
            __nv_bfloat16 h00 = __float2bfloat16(p00), h01 = __float2bfloat16(p01);
            __nv_bfloat16 h10 = __float2bfloat16(p10), h11 = __float2bfloat16(p11);
            ph1[nt] = pack2(h00, h01);
            ph2[nt] = pack2(h10, h11);
            pl1[nt] = pack2(__float2bfloat16(p00 - __bfloat162float(h00)),
                            __float2bfloat16(p01 - __bfloat162float(h01)));
            pl2[nt] = pack2(__float2bfloat16(p10 - __bfloat162float(h10)),
                            __float2bfloat16(p11 - __bfloat162float(h11)));
        }
        #pragma unroll
        for (int off = 1; off <= 2; off <<= 1) {
            rs1 += __shfl_xor_sync(0xffffffffu, rs1, off);
            rs2 += __shfl_xor_sync(0xffffffffu, rs2, off);
        }
        l1 = l1*al1 + rs1;
        l2 = l2*al2 + rs2;
        #pragma unroll
        for (int vt = 0; vt < 16; vt++) {
            O[vt][0] *= al1; O[vt][1] *= al1;
            O[vt][2] *= al2; O[vt][3] *= al2;
        }

        // O += P V  (bf16x3)
        #pragma unroll
        for (int kc = 0; kc < 4; kc++) {
            uint32_t pa[4] = { ph1[2*kc], ph2[2*kc], ph1[2*kc+1], ph2[2*kc+1] };
            uint32_t pb[4] = { pl1[2*kc], pl2[2*kc], pl1[2*kc+1], pl2[2*kc+1] };
            #pragma unroll
            for (int vp = 0; vp < 8; vp++) {
                uint32_t va = vbH + bOffV + vp*16*AV_STR + kc*32;
                uint32_t rh[4], rl[4];
                ldx4(rh, va);
                ldx4(rl, va + 18432);
                uint32_t bh0[2] = { rh[0], rh[1] }, bh1[2] = { rh[2], rh[3] };
                uint32_t bl0[2] = { rl[0], rl[1] }, bl1[2] = { rl[2], rl[3] };
                mma16816(O[2*vp],   pa, bh0);
                mma16816(O[2*vp],   pa, bl0);
                mma16816(O[2*vp],   pb, bh0);
                mma16816(O[2*vp+1], pa, bh1);
                mma16816(O[2*vp+1], pa, bl1);
                mma16816(O[2*vp+1], pb, bh1);
            }
        }
    }

    // epilogue: normalize, split hi/lo, write g_AOh/g_AOl
    const int b = bh >> 4, h = bh & 15;
    const float i1 = 1.0f / l1, i2 = 1.0f / l2;
    const size_t mrow1 = (size_t)(b*TT + qrow1) * CC;
    const size_t mrow2 = (size_t)(b*TT + qrow2) * CC;
    #pragma unroll
    for (int vt = 0; vt < 16; vt++) {
        int col = h*DD + vt*8 + 2*c4;
        float o00 = O[vt][0]*i1, o01 = O[vt][1]*i1;
        float o10 = O[vt][2]*i2, o11 = O[vt][3]*i2;
        __nv_bfloat16 h00 = __float2bfloat16(o00), h01 = __float2bfloat16(o01);
        __nv_bfloat16 h10 = __float2bfloat16(o10), h11 = __float2bfloat16(o11);
        *(__nv_bfloat162*)(g_AOh + mrow1 + col) = __halves2bfloat162(h00, h01);
        *(__nv_bfloat162*)(g_AOh + mrow2 + col) = __halves2bfloat162(h10, h11);
        *(__nv_bfloat162*)(g_AOl + mrow1 + col) = __halves2bfloat162(
            __float2bfloat16(o00 - __bfloat162float(h00)), __float2bfloat16(o01 - __bfloat162float(h01)));
        *(__nv_bfloat162*)(g_AOl + mrow2 + col) = __halves2bfloat162(
            __float2bfloat16(o10 - __bfloat162float(h10)), __float2bfloat16(o11 - __bfloat162float(h11)));
    }
}

// ---------------- launcher (no __device__ symbols as host-side args) ----------------
extern "C" void kernel_launch(void* const* d_in, const int* in_sizes, int n_in,
                              void* d_out, int out_size) {
    const float* x      = (const float*)d_in[0];
    const float* W_attn = (const float*)d_in[1];
    const float* b_attn = (const float*)d_in[2];
    const float* W_proj = (const float*)d_in[3];
    const float* b_proj = (const float*)d_in[4];
    float* out = (float*)d_out;

    cudaFuncSetAttribute(gemm_mma<0>, cudaFuncAttributeMaxDynamicSharedMemorySize, GEMM_SMEM);
    cudaFuncSetAttribute(gemm_mma<1>, cudaFuncAttributeMaxDynamicSharedMemorySize, GEMM_SMEM);
    cudaFuncSetAttribute(attn_mma_kernel, cudaFuncAttributeMaxDynamicSharedMemorySize, ATTN_SMEM);

    rope_init_kernel<<<(TT*(DD/2) + 255)/256, 256>>>();
    conv_split_kernel<<<(MM*CC/2 + 255)/256, 256>>>(x);
    conv_wT_kernel<0><<<dim3(NQKV/32, CC/32), 256>>>(W_attn);
    conv_wT_kernel<1><<<dim3(CC/32,   CC/32), 256>>>(W_proj);

    gemm_mma<0><<<(MM/128)*(NQKV/128), 256, GEMM_SMEM>>>(b_attn, nullptr);

    transpose_v_kernel<<<dim3(64, BB*HH), 256>>>();

    attn_mma_kernel<<<dim3(TT/128, BB*HH), 256, ATTN_SMEM>>>();

    gemm_mma<1><<<(MM/128)*(CC/128), 256, GEMM_SMEM>>>(b_proj, out);
}